// round 3
// baseline (speedup 1.0000x reference)
#include <cuda_runtime.h>
#include <math.h>

// Problem constants
#define BB 2
#define TT 2048
#define CCH 512
#define HH 8
#define DD 64
#define NROWS (BB*TT)   // 4096
#define C3 (3*CCH)      // 1536

// ---------------- scratch ----------------
__device__ float g_h  [NROWS*CCH];
__device__ float g_qkv[NROWS*C3];
__device__ float g_att[NROWS*CCH];
__device__ float g_y  [NROWS*CCH];
__device__ float g_y2 [NROWS*CCH];
__device__ float g_h2 [NROWS*CCH];
__device__ float g_fc [NROWS*4*CCH];

// ---------------- helpers ----------------
__device__ __forceinline__ float cvt_tf32(float x) {
    unsigned u; asm("cvt.rna.tf32.f32 %0, %1;" : "=r"(u) : "f"(x));
    return __uint_as_float(u);
}
__device__ __forceinline__ unsigned cvt_tf32_u(float x) {
    unsigned u; asm("cvt.rna.tf32.f32 %0, %1;" : "=r"(u) : "f"(x));
    return u;
}

__device__ __forceinline__ void mma_tf32(float& c0, float& c1, float& c2, float& c3,
                                         unsigned a0, unsigned a1, unsigned a2, unsigned a3,
                                         unsigned b0, unsigned b1) {
    asm volatile("mma.sync.aligned.m16n8k8.row.col.f32.tf32.tf32.f32 "
                 "{%0,%1,%2,%3}, {%4,%5,%6,%7}, {%8,%9}, {%0,%1,%2,%3};"
                 : "+f"(c0), "+f"(c1), "+f"(c2), "+f"(c3)
                 : "r"(a0), "r"(a1), "r"(a2), "r"(a3), "r"(b0), "r"(b1));
}

__device__ __forceinline__ void cp16(float* smem_dst, const float* g_src) {
    unsigned s = (unsigned)__cvta_generic_to_shared(smem_dst);
    asm volatile("cp.async.cg.shared.global [%0], [%1], 16;" :: "r"(s), "l"(g_src));
}
__device__ __forceinline__ void cp_commit() {
    asm volatile("cp.async.commit_group;" ::: "memory");
}
__device__ __forceinline__ void cp_wait0() {
    asm volatile("cp.async.wait_group 0;" ::: "memory");
}

// fast sigmoid: FMA-pipe only
__device__ __forceinline__ float sigmoid_fast(float x) {
    float t = x * -1.4426950408889634f;
    t = fminf(fmaxf(t, -20.0f), 20.0f);
    float fi = floorf(t);
    float f  = t - fi;
    float p = 1.5403530393e-4f;
    p = fmaf(p, f, 1.3333558146e-3f);
    p = fmaf(p, f, 9.6181291076e-3f);
    p = fmaf(p, f, 5.5504108664e-2f);
    p = fmaf(p, f, 2.4022650696e-1f);
    p = fmaf(p, f, 6.9314718056e-1f);
    p = fmaf(p, f, 1.0f);
    float r = __int_as_float(((int)fi + 127) << 23) * p;
    float a = 1.0f + r;
    float y = __int_as_float(0x7EF127EA - __float_as_int(a));
    y = y * (2.0f - a * y);
    y = y * (2.0f - a * y);
    y = y * (2.0f - a * y);
    return y;
}

// ---------------- LayerNorm ----------------
__global__ __launch_bounds__(128) void ln_kernel(const float* __restrict__ x,
                                                 const float* __restrict__ g,
                                                 const float* __restrict__ bta,
                                                 float* __restrict__ out)
{
    int row = blockIdx.x;
    int t = threadIdx.x;
    const float4* xr = (const float4*)(x + (size_t)row * CCH);
    float4 v = xr[t];
    float s  = v.x + v.y + v.z + v.w;
    float s2 = v.x*v.x + v.y*v.y + v.z*v.z + v.w*v.w;
    #pragma unroll
    for (int o = 16; o; o >>= 1) {
        s  += __shfl_xor_sync(0xffffffffu, s,  o);
        s2 += __shfl_xor_sync(0xffffffffu, s2, o);
    }
    __shared__ float ss[4], ss2[4];
    int w = t >> 5, l = t & 31;
    if (l == 0) { ss[w] = s; ss2[w] = s2; }
    __syncthreads();
    s  = ss[0]  + ss[1]  + ss[2]  + ss[3];
    s2 = ss2[0] + ss2[1] + ss2[2] + ss2[3];
    float m   = s  * (1.0f/512.0f);
    float var = s2 * (1.0f/512.0f) - m*m;
    float r   = rsqrtf(var + 1e-5f);
    float4 gv = ((const float4*)g)[t];
    float4 bv = ((const float4*)bta)[t];
    float4 o4;
    o4.x = (v.x - m) * r * gv.x + bv.x;
    o4.y = (v.y - m) * r * gv.y + bv.y;
    o4.z = (v.z - m) * r * gv.z + bv.z;
    o4.w = (v.w - m) * r * gv.w + bv.w;
    ((float4*)(out + (size_t)row * CCH))[t] = o4;
}

// ---------------- TF32 tensor-core GEMM (cp.async double-buffered) ----------------
// template over tile size. BK=32. Warp N-tile fixed at 32 (nt=4 x n8).
// As [2][BM][36], Bs [2][32][BN+8]; both frag patterns conflict-free.
template<int BM, int BN, int THREADS, bool HAS_ADD, bool GELU_EPI>
__global__ __launch_bounds__(THREADS, (THREADS == 256) ? 2 : 4) void gemm_tf32(
    const float* __restrict__ A, const float* __restrict__ W,
    const float* __restrict__ bias, const float* __restrict__ addm,
    float* __restrict__ Cmat, int M, int N, int K)
{
    constexpr int AS_STRIDE = 36;
    constexpr int BS_STRIDE = BN + 8;
    constexpr int AS_SZ = BM * AS_STRIDE;
    constexpr int BS_SZ = 32 * BS_STRIDE;
    constexpr int WARPS = THREADS / 32;
    constexpr int WARP_COLS = BN / 32;
    constexpr int WARP_ROWS = WARPS / WARP_COLS;
    constexpr int WM = BM / WARP_ROWS;
    constexpr int MT = WM / 16;
    constexpr int A_STEP = THREADS / 8;
    constexpr int NB4 = BN / 4;

    extern __shared__ float sh[];
    float* As = sh;
    float* Bs = sh + 2*AS_SZ;

    const int tid  = threadIdx.x;
    const int warp = tid >> 5, lane = tid & 31;
    const int gid  = lane >> 2, tig = lane & 3;
    const int wm   = (warp / WARP_COLS) * WM;
    const int wn   = (warp % WARP_COLS) * 32;
    const int bm   = blockIdx.y * BM, bn = blockIdx.x * BN;

    const int ar = tid >> 3, ac = (tid & 7) * 4;
    const int br = tid / NB4, bc = (tid % NB4) * 4;

    const float* Ag = A + (size_t)bm * K;
    const float* Wg = W + bn;

    float acc[MT][4][4];
    #pragma unroll
    for (int i = 0; i < MT; i++)
        #pragma unroll
        for (int j = 0; j < 4; j++)
            { acc[i][j][0]=0.f; acc[i][j][1]=0.f; acc[i][j][2]=0.f; acc[i][j][3]=0.f; }

    const int nk = K >> 5;

    // prologue: async-load stage 0
    {
        #pragma unroll
        for (int i = 0; i < 4; i++)
            cp16(As + (ar + i*A_STEP)*AS_STRIDE + ac, Ag + (size_t)(ar + i*A_STEP) * K + ac);
        #pragma unroll
        for (int i = 0; i < 4; i++)
            cp16(Bs + (br + i*8)*BS_STRIDE + bc, Wg + (size_t)(br + i*8) * N + bc);
        cp_commit();
    }

    for (int kt = 0; kt < nk; kt++) {
        cp_wait0();
        __syncthreads();
        if (kt + 1 < nk) {   // issue next stage (safe: all warps past barrier)
            int k0 = (kt + 1) << 5;
            float* asn = As + ((kt + 1) & 1) * AS_SZ;
            float* bsn = Bs + ((kt + 1) & 1) * BS_SZ;
            #pragma unroll
            for (int i = 0; i < 4; i++)
                cp16(asn + (ar + i*A_STEP)*AS_STRIDE + ac, Ag + (size_t)(ar + i*A_STEP) * K + k0 + ac);
            #pragma unroll
            for (int i = 0; i < 4; i++)
                cp16(bsn + (br + i*8)*BS_STRIDE + bc, Wg + (size_t)(k0 + br + i*8) * N + bc);
            cp_commit();
        }
        const float* as = As + (kt & 1) * AS_SZ;
        const float* bs = Bs + (kt & 1) * BS_SZ;
        #pragma unroll
        for (int ks = 0; ks < 4; ks++) {
            unsigned af[MT][4], bf[4][2];
            #pragma unroll
            for (int mt = 0; mt < MT; mt++) {
                const float* ap = as + (wm + mt*16 + gid)*AS_STRIDE + ks*8 + tig;
                af[mt][0] = cvt_tf32_u(ap[0]);
                af[mt][1] = cvt_tf32_u(ap[8*AS_STRIDE]);
                af[mt][2] = cvt_tf32_u(ap[4]);
                af[mt][3] = cvt_tf32_u(ap[8*AS_STRIDE + 4]);
            }
            #pragma unroll
            for (int nt = 0; nt < 4; nt++) {
                const float* bp = bs + (ks*8 + tig)*BS_STRIDE + wn + nt*8 + gid;
                bf[nt][0] = cvt_tf32_u(bp[0]);
                bf[nt][1] = cvt_tf32_u(bp[4*BS_STRIDE]);
            }
            #pragma unroll
            for (int mt = 0; mt < MT; mt++)
                #pragma unroll
                for (int nt = 0; nt < 4; nt++)
                    mma_tf32(acc[mt][nt][0], acc[mt][nt][1], acc[mt][nt][2], acc[mt][nt][3],
                             af[mt][0], af[mt][1], af[mt][2], af[mt][3],
                             bf[nt][0], bf[nt][1]);
        }
    }

    // epilogue
    #pragma unroll
    for (int mt = 0; mt < MT; mt++) {
        int r0 = bm + wm + mt*16 + gid;
        #pragma unroll
        for (int nt = 0; nt < 4; nt++) {
            int c0 = bn + wn + nt*8 + 2*tig;
            float2 bv = *(const float2*)(bias + c0);
            float v0 = acc[mt][nt][0] + bv.x;
            float v1 = acc[mt][nt][1] + bv.y;
            float v2 = acc[mt][nt][2] + bv.x;
            float v3 = acc[mt][nt][3] + bv.y;
            size_t o0 = (size_t)r0 * N + c0;
            size_t o1 = (size_t)(r0 + 8) * N + c0;
            if (HAS_ADD) {
                float2 d0 = *(const float2*)(addm + o0);
                float2 d1 = *(const float2*)(addm + o1);
                v0 += d0.x; v1 += d0.y; v2 += d1.x; v3 += d1.y;
            }
            if (GELU_EPI) {
                v0 = 0.5f * v0 * (1.0f + erff(v0 * 0.70710678118654752f));
                v1 = 0.5f * v1 * (1.0f + erff(v1 * 0.70710678118654752f));
                v2 = 0.5f * v2 * (1.0f + erff(v2 * 0.70710678118654752f));
                v3 = 0.5f * v3 * (1.0f + erff(v3 * 0.70710678118654752f));
            }
            *(float2*)(Cmat + o0) = make_float2(v0, v1);
            *(float2*)(Cmat + o1) = make_float2(v2, v3);
        }
    }
}

// ---------------- TF32 tensor-core attention ----------------
// grid (bh, t-tile) -> heads of one (b,t-slab) co-resident => coulomb shared in L2.
// Double-buffered K/V (register-staged LDG + cvt + STS), single syncthreads/iter.
// Coulomb prefetched into regs before the QK mma.
#define A_QS_STRIDE 68
#define A_KS_STRIDE 68
#define A_VS_STRIDE 72
#define A_SS_STRIDE 68
#define A_KS_SZ (64*A_KS_STRIDE)
#define A_VS_SZ (64*A_VS_STRIDE)
#define A_SMEM ((128*A_QS_STRIDE + 2*A_KS_SZ + 2*A_VS_SZ + 128*A_SS_STRIDE)*4)

__global__ __launch_bounds__(256) void attn_tf32(const float* __restrict__ qkv,
                                                 const float* __restrict__ coul,
                                                 float* __restrict__ yatt)
{
    extern __shared__ float sh[];
    float* Qs = sh;
    float* Ks = Qs + 128*A_QS_STRIDE;
    float* Vs = Ks + 2*A_KS_SZ;
    float* Ss = Vs + 2*A_VS_SZ;

    int bh = blockIdx.x;               // heads fastest -> co-resident share coulomb
    int b = bh >> 3, h = bh & 7;
    int t0 = blockIdx.y * 128;
    int tid = threadIdx.x, warp = tid >> 5, lane = tid & 31;
    int gid = lane >> 2, tig = lane & 3;

    const int lr = tid >> 4, lc = (tid & 15) * 4;   // K/V loader coords

    // load Q (scaled by 1/8, tf32)
    const float* qb = qkv + (size_t)(b*TT + t0) * C3 + h*DD;
    #pragma unroll
    for (int i = 0; i < 8; i++) {
        float4 v = *(const float4*)(qb + (size_t)(lr + i*16) * C3 + lc);
        float* p = Qs + (lr + i*16)*A_QS_STRIDE + lc;
        p[0]=cvt_tf32(v.x*0.125f); p[1]=cvt_tf32(v.y*0.125f);
        p[2]=cvt_tf32(v.z*0.125f); p[3]=cvt_tf32(v.w*0.125f);
    }

    float yacc[8][4];
    #pragma unroll
    for (int i = 0; i < 8; i++) { yacc[i][0]=0.f; yacc[i][1]=0.f; yacc[i][2]=0.f; yacc[i][3]=0.f; }

    const float* cb = coul + (size_t)b * TT * TT;
    const int r0 = warp*16 + gid;

    const float* kbase = qkv + (size_t)(b*TT) * C3 + CCH + h*DD;

    float4 kreg[4], vreg[4];
    // prologue LDG for s-tile 0
    #pragma unroll
    for (int i = 0; i < 4; i++) {
        const float* kb = kbase + (size_t)(lr + i*16) * C3 + lc;
        kreg[i] = *(const float4*)(kb);
        vreg[i] = *(const float4*)(kb + CCH);
    }

    for (int kt = 0; kt < TT/64; kt++) {
        const int s0 = kt * 64;
        float* ksb = Ks + (kt & 1) * A_KS_SZ;
        float* vsb = Vs + (kt & 1) * A_VS_SZ;
        // STS (cvt to tf32)
        #pragma unroll
        for (int i = 0; i < 4; i++) {
            float* pk = ksb + (lr + i*16)*A_KS_STRIDE + lc;
            pk[0]=cvt_tf32(kreg[i].x); pk[1]=cvt_tf32(kreg[i].y);
            pk[2]=cvt_tf32(kreg[i].z); pk[3]=cvt_tf32(kreg[i].w);
            float* pv = vsb + (lr + i*16)*A_VS_STRIDE + lc;
            pv[0]=cvt_tf32(vreg[i].x); pv[1]=cvt_tf32(vreg[i].y);
            pv[2]=cvt_tf32(vreg[i].z); pv[3]=cvt_tf32(vreg[i].w);
        }
        __syncthreads();

        // prefetch coulomb for THIS tile (latency hides under QK mma)
        float2 creg0[8], creg1[8];
        #pragma unroll
        for (int nt = 0; nt < 8; nt++) {
            int sc = s0 + nt*8 + 2*tig;
            creg0[nt] = *(const float2*)(cb + (size_t)(t0 + r0)     * TT + sc);
            creg1[nt] = *(const float2*)(cb + (size_t)(t0 + r0 + 8) * TT + sc);
        }
        // prefetch next K/V tile into regs (latency hides under compute)
        if (kt + 1 < TT/64) {
            #pragma unroll
            for (int i = 0; i < 4; i++) {
                const float* kb = kbase + (size_t)(s0 + 64 + lr + i*16) * C3 + lc;
                kreg[i] = *(const float4*)(kb);
                vreg[i] = *(const float4*)(kb + CCH);
            }
        }

        // S = Q @ K^T
        float sacc[8][4];
        #pragma unroll
        for (int i = 0; i < 8; i++) { sacc[i][0]=0.f; sacc[i][1]=0.f; sacc[i][2]=0.f; sacc[i][3]=0.f; }
        #pragma unroll
        for (int ks = 0; ks < 8; ks++) {
            const float* ap = Qs + r0*A_QS_STRIDE + ks*8 + tig;
            unsigned a0 = __float_as_uint(ap[0]);
            unsigned a1 = __float_as_uint(ap[8*A_QS_STRIDE]);
            unsigned a2 = __float_as_uint(ap[4]);
            unsigned a3 = __float_as_uint(ap[8*A_QS_STRIDE + 4]);
            #pragma unroll
            for (int nt = 0; nt < 8; nt++) {
                const float* bp = ksb + (nt*8 + gid)*A_KS_STRIDE + ks*8 + tig;
                mma_tf32(sacc[nt][0], sacc[nt][1], sacc[nt][2], sacc[nt][3],
                         a0, a1, a2, a3,
                         __float_as_uint(bp[0]), __float_as_uint(bp[4]));
            }
        }

        // sigmoid * coulomb -> Ss (warp-private rows)
        #pragma unroll
        for (int nt = 0; nt < 8; nt++) {
            int sc = nt*8 + 2*tig;
            float* sp = Ss + r0*A_SS_STRIDE + sc;
            sp[0]                 = cvt_tf32(sigmoid_fast(sacc[nt][0]) * creg0[nt].x);
            sp[1]                 = cvt_tf32(sigmoid_fast(sacc[nt][1]) * creg0[nt].y);
            sp[8*A_SS_STRIDE]     = cvt_tf32(sigmoid_fast(sacc[nt][2]) * creg1[nt].x);
            sp[8*A_SS_STRIDE + 1] = cvt_tf32(sigmoid_fast(sacc[nt][3]) * creg1[nt].y);
        }
        __syncwarp();

        // Y += S @ V
        #pragma unroll
        for (int ks = 0; ks < 8; ks++) {
            const float* ap = Ss + r0*A_SS_STRIDE + ks*8 + tig;
            unsigned a0 = __float_as_uint(ap[0]);
            unsigned a1 = __float_as_uint(ap[8*A_SS_STRIDE]);
            unsigned a2 = __float_as_uint(ap[4]);
            unsigned a3 = __float_as_uint(ap[8*A_SS_STRIDE + 4]);
            #pragma unroll
            for (int nt = 0; nt < 8; nt++) {
                const float* bp = vsb + (ks*8 + tig)*A_VS_STRIDE + nt*8 + gid;
                mma_tf32(yacc[nt][0], yacc[nt][1], yacc[nt][2], yacc[nt][3],
                         a0, a1, a2, a3,
                         __float_as_uint(bp[0]), __float_as_uint(bp[4*A_VS_STRIDE]));
            }
        }
        // no trailing sync: next iter writes the OTHER K/V buffer; its last
        // readers all passed this iteration's syncthreads.
    }

    // store Y
    float* ob = yatt + (size_t)(b*TT + t0 + r0) * CCH + h*DD;
    #pragma unroll
    for (int nt = 0; nt < 8; nt++) {
        int c = nt*8 + 2*tig;
        *(float2*)(ob + c)           = make_float2(yacc[nt][0], yacc[nt][1]);
        *(float2*)(ob + 8*CCH + c)   = make_float2(yacc[nt][2], yacc[nt][3]);
    }
}

// ---------------- launch ----------------
#define G_SMEM_128 ((2*128*36 + 2*32*136)*4)
#define G_SMEM_64  ((2*64*36  + 2*32*72 )*4)

extern "C" void kernel_launch(void* const* d_in, const int* in_sizes, int n_in,
                              void* d_out, int out_size)
{
    const float* x      = (const float*)d_in[0];
    const float* coul   = (const float*)d_in[2];
    const float* ln1g   = (const float*)d_in[3];
    const float* ln1b   = (const float*)d_in[4];
    const float* w_attn = (const float*)d_in[5];
    const float* b_attn = (const float*)d_in[6];
    const float* w_self = (const float*)d_in[7];
    const float* b_self = (const float*)d_in[8];
    const float* w_proj = (const float*)d_in[9];
    const float* b_proj = (const float*)d_in[10];
    const float* ln2g   = (const float*)d_in[11];
    const float* ln2b   = (const float*)d_in[12];
    const float* w_fc   = (const float*)d_in[13];
    const float* b_fc   = (const float*)d_in[14];
    const float* w_fcp  = (const float*)d_in[15];
    const float* b_fcp  = (const float*)d_in[16];
    float* out = (float*)d_out;

    float *h, *qkvp, *attp, *yp, *y2p, *h2p, *fcp;
    cudaGetSymbolAddress((void**)&h,    g_h);
    cudaGetSymbolAddress((void**)&qkvp, g_qkv);
    cudaGetSymbolAddress((void**)&attp, g_att);
    cudaGetSymbolAddress((void**)&yp,   g_y);
    cudaGetSymbolAddress((void**)&y2p,  g_y2);
    cudaGetSymbolAddress((void**)&h2p,  g_h2);
    cudaGetSymbolAddress((void**)&fcp,  g_fc);

    cudaFuncSetAttribute((const void*)gemm_tf32<128,128,256,false,false>, cudaFuncAttributeMaxDynamicSharedMemorySize, G_SMEM_128);
    cudaFuncSetAttribute((const void*)gemm_tf32<128,128,256,false,true>,  cudaFuncAttributeMaxDynamicSharedMemorySize, G_SMEM_128);
    cudaFuncSetAttribute((const void*)gemm_tf32<64,64,128,true,false>,    cudaFuncAttributeMaxDynamicSharedMemorySize, G_SMEM_64);
    cudaFuncSetAttribute((const void*)gemm_tf32<64,64,128,false,false>,   cudaFuncAttributeMaxDynamicSharedMemorySize, G_SMEM_64);
    cudaFuncSetAttribute(attn_tf32, cudaFuncAttributeMaxDynamicSharedMemorySize, A_SMEM);

    // 1) h = LN1(x)
    ln_kernel<<<NROWS, 128>>>(x, ln1g, ln1b, h);
    // 2) qkv = h @ w_attn + b_attn           [4096 x 1536], k=512
    gemm_tf32<128,128,256,false,false><<<dim3(12,32), 256, G_SMEM_128>>>(h, w_attn, b_attn, nullptr, qkvp, NROWS, C3, CCH);
    // 3) fused sigmoid-attention (bh fastest for coulomb L2 sharing)
    attn_tf32<<<dim3(BB*HH, TT/128), 256, A_SMEM>>>(qkvp, coul, attp);
    // 4) y = att + h @ w_self + b_self       [4096 x 512]
    gemm_tf32<64,64,128,true,false><<<dim3(8,64), 128, G_SMEM_64>>>(h, w_self, b_self, attp, yp, NROWS, CCH, CCH);
    // 5) y2 = y @ w_proj + b_proj            [4096 x 512]
    gemm_tf32<64,64,128,false,false><<<dim3(8,64), 128, G_SMEM_64>>>(yp, w_proj, b_proj, nullptr, y2p, NROWS, CCH, CCH);
    // 6) h2 = LN2(y2)
    ln_kernel<<<NROWS, 128>>>(y2p, ln2g, ln2b, h2p);
    // 7) fc = gelu(h2 @ w_fc + b_fc)         [4096 x 2048]
    gemm_tf32<128,128,256,false,true><<<dim3(16,32), 256, G_SMEM_128>>>(h2p, w_fc, b_fc, nullptr, fcp, NROWS, 4*CCH, CCH);
    // 8) out = fc @ w_fc_proj + b_fc_proj    [4096 x 512], k=2048
    gemm_tf32<64,64,128,false,false><<<dim3(8,64), 128, G_SMEM_64>>>(fcp, w_fcp, b_fcp, nullptr, out, NROWS, CCH, 4*CCH);
}

// round 6
// speedup vs baseline: 1.0637x; 1.0637x over previous
#include <cuda_runtime.h>
#include <math.h>

// Problem constants
#define BB 2
#define TT 2048
#define CCH 512
#define HH 8
#define DD 64
#define NROWS (BB*TT)   // 4096
#define C3 (3*CCH)      // 1536

// ---------------- scratch ----------------
__device__ float g_h  [NROWS*CCH];
__device__ float g_qkv[NROWS*C3];
__device__ float g_att[NROWS*CCH];
__device__ float g_y  [NROWS*CCH];
__device__ float g_y2 [NROWS*CCH];
__device__ float g_h2 [NROWS*CCH];
__device__ float g_fc [NROWS*4*CCH];
// pre-rounded (tf32) weights
__device__ float g_wattn[CCH*C3];
__device__ float g_wself[CCH*CCH];
__device__ float g_wproj[CCH*CCH];
__device__ float g_wfc  [CCH*4*CCH];
__device__ float g_wfcp [4*CCH*CCH];

// ---------------- helpers ----------------
__device__ __forceinline__ float cvt_tf32(float x) {
    unsigned u; asm("cvt.rna.tf32.f32 %0, %1;" : "=r"(u) : "f"(x));
    return __uint_as_float(u);
}

__device__ __forceinline__ void mma_tf32(float& c0, float& c1, float& c2, float& c3,
                                         unsigned a0, unsigned a1, unsigned a2, unsigned a3,
                                         unsigned b0, unsigned b1) {
    asm volatile("mma.sync.aligned.m16n8k8.row.col.f32.tf32.tf32.f32 "
                 "{%0,%1,%2,%3}, {%4,%5,%6,%7}, {%8,%9}, {%0,%1,%2,%3};"
                 : "+f"(c0), "+f"(c1), "+f"(c2), "+f"(c3)
                 : "r"(a0), "r"(a1), "r"(a2), "r"(a3), "r"(b0), "r"(b1));
}

__device__ __forceinline__ void cp16(float* smem_dst, const float* g_src) {
    unsigned s = (unsigned)__cvta_generic_to_shared(smem_dst);
    asm volatile("cp.async.cg.shared.global [%0], [%1], 16;" :: "r"(s), "l"(g_src));
}
__device__ __forceinline__ void cp_commit() {
    asm volatile("cp.async.commit_group;" ::: "memory");
}
__device__ __forceinline__ void cp_wait0() {
    asm volatile("cp.async.wait_group 0;" ::: "memory");
}

// fast sigmoid: FMA-pipe only
__device__ __forceinline__ float sigmoid_fast(float x) {
    float t = x * -1.4426950408889634f;
    t = fminf(fmaxf(t, -20.0f), 20.0f);
    float fi = floorf(t);
    float f  = t - fi;
    float p = 1.5403530393e-4f;
    p = fmaf(p, f, 1.3333558146e-3f);
    p = fmaf(p, f, 9.6181291076e-3f);
    p = fmaf(p, f, 5.5504108664e-2f);
    p = fmaf(p, f, 2.4022650696e-1f);
    p = fmaf(p, f, 6.9314718056e-1f);
    p = fmaf(p, f, 1.0f);
    float r = __int_as_float(((int)fi + 127) << 23) * p;
    float a = 1.0f + r;
    float y = __int_as_float(0x7EF127EA - __float_as_int(a));
    y = y * (2.0f - a * y);
    y = y * (2.0f - a * y);
    y = y * (2.0f - a * y);
    return y;
}

// ---------------- weight pre-round ----------------
__global__ __launch_bounds__(256) void cvt4_kernel(const float4* __restrict__ in,
                                                   float4* __restrict__ out, int n4)
{
    int i = blockIdx.x * 256 + threadIdx.x;
    if (i < n4) {
        float4 v = in[i];
        v.x = cvt_tf32(v.x); v.y = cvt_tf32(v.y);
        v.z = cvt_tf32(v.z); v.w = cvt_tf32(v.w);
        out[i] = v;
    }
}

// ---------------- LayerNorm (output rounded to tf32: feeds MMA A) ----------------
__global__ __launch_bounds__(128) void ln_kernel(const float* __restrict__ x,
                                                 const float* __restrict__ g,
                                                 const float* __restrict__ bta,
                                                 float* __restrict__ out)
{
    int row = blockIdx.x;
    int t = threadIdx.x;
    const float4* xr = (const float4*)(x + (size_t)row * CCH);
    float4 v = xr[t];
    float s  = v.x + v.y + v.z + v.w;
    float s2 = v.x*v.x + v.y*v.y + v.z*v.z + v.w*v.w;
    #pragma unroll
    for (int o = 16; o; o >>= 1) {
        s  += __shfl_xor_sync(0xffffffffu, s,  o);
        s2 += __shfl_xor_sync(0xffffffffu, s2, o);
    }
    __shared__ float ss[4], ss2[4];
    int w = t >> 5, l = t & 31;
    if (l == 0) { ss[w] = s; ss2[w] = s2; }
    __syncthreads();
    s  = ss[0]  + ss[1]  + ss[2]  + ss[3];
    s2 = ss2[0] + ss2[1] + ss2[2] + ss2[3];
    float m   = s  * (1.0f/512.0f);
    float var = s2 * (1.0f/512.0f) - m*m;
    float r   = rsqrtf(var + 1e-5f);
    float4 gv = ((const float4*)g)[t];
    float4 bv = ((const float4*)bta)[t];
    float4 o4;
    o4.x = cvt_tf32((v.x - m) * r * gv.x + bv.x);
    o4.y = cvt_tf32((v.y - m) * r * gv.y + bv.y);
    o4.z = cvt_tf32((v.z - m) * r * gv.z + bv.z);
    o4.w = cvt_tf32((v.w - m) * r * gv.w + bv.w);
    ((float4*)(out + (size_t)row * CCH))[t] = o4;
}

// ---------------- TF32 tensor-core GEMM (cp.async, inputs pre-rounded) ----------------
// No cvt in the inner loop. Warp N-tile fixed at 32 (nt=4 x n8).
template<int BM, int BN, int THREADS, bool HAS_ADD, bool GELU_EPI, bool ROUND_OUT>
__global__ __launch_bounds__(THREADS, 2) void gemm_tf32(
    const float* __restrict__ A, const float* __restrict__ W,
    const float* __restrict__ bias, const float* __restrict__ addm,
    float* __restrict__ Cmat, int M, int N, int K)
{
    constexpr int AS_STRIDE = 36;
    constexpr int BS_STRIDE = BN + 8;
    constexpr int AS_SZ = BM * AS_STRIDE;
    constexpr int BS_SZ = 32 * BS_STRIDE;
    constexpr int WARPS = THREADS / 32;
    constexpr int WARP_COLS = BN / 32;
    constexpr int WARP_ROWS = WARPS / WARP_COLS;
    constexpr int WM = BM / WARP_ROWS;
    constexpr int MT = WM / 16;
    constexpr int A_ITERS = (BM * 8) / THREADS;
    constexpr int A_STEP = THREADS / 8;
    constexpr int NB4 = BN / 4;
    constexpr int B_ITERS = (8 * BN) / THREADS;
    constexpr int B_STEP = THREADS / NB4;

    extern __shared__ float sh[];
    float* As = sh;
    float* Bs = sh + 2*AS_SZ;

    const int tid  = threadIdx.x;
    const int warp = tid >> 5, lane = tid & 31;
    const int gid  = lane >> 2, tig = lane & 3;
    const int wm   = (warp / WARP_COLS) * WM;
    const int wn   = (warp % WARP_COLS) * 32;
    const int bm   = blockIdx.y * BM, bn = blockIdx.x * BN;

    const int ar = tid >> 3, ac = (tid & 7) * 4;
    const int br = tid / NB4, bc = (tid % NB4) * 4;

    const float* Ag = A + (size_t)bm * K;
    const float* Wg = W + bn;

    float acc[MT][4][4];
    #pragma unroll
    for (int i = 0; i < MT; i++)
        #pragma unroll
        for (int j = 0; j < 4; j++)
            { acc[i][j][0]=0.f; acc[i][j][1]=0.f; acc[i][j][2]=0.f; acc[i][j][3]=0.f; }

    const int nk = K >> 5;

    // prologue: async-load stage 0
    #pragma unroll
    for (int i = 0; i < A_ITERS; i++)
        cp16(As + (ar + i*A_STEP)*AS_STRIDE + ac, Ag + (size_t)(ar + i*A_STEP) * K + ac);
    #pragma unroll
    for (int i = 0; i < B_ITERS; i++)
        cp16(Bs + (br + i*B_STEP)*BS_STRIDE + bc, Wg + (size_t)(br + i*B_STEP) * N + bc);
    cp_commit();

    for (int kt = 0; kt < nk; kt++) {
        cp_wait0();
        __syncthreads();
        if (kt + 1 < nk) {
            int k0 = (kt + 1) << 5;
            float* asn = As + ((kt + 1) & 1) * AS_SZ;
            float* bsn = Bs + ((kt + 1) & 1) * BS_SZ;
            #pragma unroll
            for (int i = 0; i < A_ITERS; i++)
                cp16(asn + (ar + i*A_STEP)*AS_STRIDE + ac, Ag + (size_t)(ar + i*A_STEP) * K + k0 + ac);
            #pragma unroll
            for (int i = 0; i < B_ITERS; i++)
                cp16(bsn + (br + i*B_STEP)*BS_STRIDE + bc, Wg + (size_t)(k0 + br + i*B_STEP) * N + bc);
            cp_commit();
        }
        const float* as = As + (kt & 1) * AS_SZ;
        const float* bs = Bs + (kt & 1) * BS_SZ;
        #pragma unroll
        for (int ks = 0; ks < 4; ks++) {
            unsigned af[MT][4], bf[4][2];
            #pragma unroll
            for (int mt = 0; mt < MT; mt++) {
                const float* ap = as + (wm + mt*16 + gid)*AS_STRIDE + ks*8 + tig;
                af[mt][0] = __float_as_uint(ap[0]);
                af[mt][1] = __float_as_uint(ap[8*AS_STRIDE]);
                af[mt][2] = __float_as_uint(ap[4]);
                af[mt][3] = __float_as_uint(ap[8*AS_STRIDE + 4]);
            }
            #pragma unroll
            for (int nt = 0; nt < 4; nt++) {
                const float* bp = bs + (ks*8 + tig)*BS_STRIDE + wn + nt*8 + gid;
                bf[nt][0] = __float_as_uint(bp[0]);
                bf[nt][1] = __float_as_uint(bp[4*BS_STRIDE]);
            }
            #pragma unroll
            for (int mt = 0; mt < MT; mt++)
                #pragma unroll
                for (int nt = 0; nt < 4; nt++)
                    mma_tf32(acc[mt][nt][0], acc[mt][nt][1], acc[mt][nt][2], acc[mt][nt][3],
                             af[mt][0], af[mt][1], af[mt][2], af[mt][3],
                             bf[nt][0], bf[nt][1]);
        }
    }

    // epilogue
    #pragma unroll
    for (int mt = 0; mt < MT; mt++) {
        int r0 = bm + wm + mt*16 + gid;
        #pragma unroll
        for (int nt = 0; nt < 4; nt++) {
            int c0 = bn + wn + nt*8 + 2*tig;
            float2 bv = *(const float2*)(bias + c0);
            float v0 = acc[mt][nt][0] + bv.x;
            float v1 = acc[mt][nt][1] + bv.y;
            float v2 = acc[mt][nt][2] + bv.x;
            float v3 = acc[mt][nt][3] + bv.y;
            size_t o0 = (size_t)r0 * N + c0;
            size_t o1 = (size_t)(r0 + 8) * N + c0;
            if (HAS_ADD) {
                float2 d0 = *(const float2*)(addm + o0);
                float2 d1 = *(const float2*)(addm + o1);
                v0 += d0.x; v1 += d0.y; v2 += d1.x; v3 += d1.y;
            }
            if (GELU_EPI) {
                v0 = 0.5f * v0 * (1.0f + erff(v0 * 0.70710678118654752f));
                v1 = 0.5f * v1 * (1.0f + erff(v1 * 0.70710678118654752f));
                v2 = 0.5f * v2 * (1.0f + erff(v2 * 0.70710678118654752f));
                v3 = 0.5f * v3 * (1.0f + erff(v3 * 0.70710678118654752f));
            }
            if (ROUND_OUT) {
                v0 = cvt_tf32(v0); v1 = cvt_tf32(v1);
                v2 = cvt_tf32(v2); v3 = cvt_tf32(v3);
            }
            *(float2*)(Cmat + o0) = make_float2(v0, v1);
            *(float2*)(Cmat + o1) = make_float2(v2, v3);
        }
    }
}

// ---------------- TF32 tensor-core attention (qkv pre-rounded -> no cvt on Q/K/V) ----------------
#define A_QS_STRIDE 68
#define A_KS_STRIDE 68
#define A_VS_STRIDE 72
#define A_SS_STRIDE 68
#define A_KS_SZ (64*A_KS_STRIDE)
#define A_VS_SZ (64*A_VS_STRIDE)
#define A_SMEM ((128*A_QS_STRIDE + 2*A_KS_SZ + 2*A_VS_SZ + 128*A_SS_STRIDE)*4)

__global__ __launch_bounds__(256) void attn_tf32(const float* __restrict__ qkv,
                                                 const float* __restrict__ coul,
                                                 float* __restrict__ yatt)
{
    extern __shared__ float sh[];
    float* Qs = sh;
    float* Ks = Qs + 128*A_QS_STRIDE;
    float* Vs = Ks + 2*A_KS_SZ;
    float* Ss = Vs + 2*A_VS_SZ;

    int bh = blockIdx.x;               // heads fastest -> coulomb shared in L2
    int b = bh >> 3, h = bh & 7;
    int t0 = blockIdx.y * 128;
    int tid = threadIdx.x, warp = tid >> 5, lane = tid & 31;
    int gid = lane >> 2, tig = lane & 3;

    const int lr = tid >> 4, lc = (tid & 15) * 4;

    // load Q (x 1/8 exact; values pre-rounded tf32)
    const float* qb = qkv + (size_t)(b*TT + t0) * C3 + h*DD;
    #pragma unroll
    for (int i = 0; i < 8; i++) {
        float4 v = *(const float4*)(qb + (size_t)(lr + i*16) * C3 + lc);
        float* p = Qs + (lr + i*16)*A_QS_STRIDE + lc;
        p[0]=v.x*0.125f; p[1]=v.y*0.125f; p[2]=v.z*0.125f; p[3]=v.w*0.125f;
    }

    float yacc[8][4];
    #pragma unroll
    for (int i = 0; i < 8; i++) { yacc[i][0]=0.f; yacc[i][1]=0.f; yacc[i][2]=0.f; yacc[i][3]=0.f; }

    const float* cb = coul + (size_t)b * TT * TT;
    const int r0 = warp*16 + gid;

    const float* kbase = qkv + (size_t)(b*TT) * C3 + CCH + h*DD;

    float4 kreg[4], vreg[4];
    #pragma unroll
    for (int i = 0; i < 4; i++) {
        const float* kb = kbase + (size_t)(lr + i*16) * C3 + lc;
        kreg[i] = *(const float4*)(kb);
        vreg[i] = *(const float4*)(kb + CCH);
    }

    for (int kt = 0; kt < TT/64; kt++) {
        const int s0 = kt * 64;
        float* ksb = Ks + (kt & 1) * A_KS_SZ;
        float* vsb = Vs + (kt & 1) * A_VS_SZ;
        #pragma unroll
        for (int i = 0; i < 4; i++) {
            float* pk = ksb + (lr + i*16)*A_KS_STRIDE + lc;
            pk[0]=kreg[i].x; pk[1]=kreg[i].y; pk[2]=kreg[i].z; pk[3]=kreg[i].w;
            float* pv = vsb + (lr + i*16)*A_VS_STRIDE + lc;
            pv[0]=vreg[i].x; pv[1]=vreg[i].y; pv[2]=vreg[i].z; pv[3]=vreg[i].w;
        }
        __syncthreads();

        // coulomb prefetch for this tile
        float2 creg0[8], creg1[8];
        #pragma unroll
        for (int nt = 0; nt < 8; nt++) {
            int sc = s0 + nt*8 + 2*tig;
            creg0[nt] = *(const float2*)(cb + (size_t)(t0 + r0)     * TT + sc);
            creg1[nt] = *(const float2*)(cb + (size_t)(t0 + r0 + 8) * TT + sc);
        }
        // next K/V tile prefetch
        if (kt + 1 < TT/64) {
            #pragma unroll
            for (int i = 0; i < 4; i++) {
                const float* kb = kbase + (size_t)(s0 + 64 + lr + i*16) * C3 + lc;
                kreg[i] = *(const float4*)(kb);
                vreg[i] = *(const float4*)(kb + CCH);
            }
        }

        // S = Q @ K^T
        float sacc[8][4];
        #pragma unroll
        for (int i = 0; i < 8; i++) { sacc[i][0]=0.f; sacc[i][1]=0.f; sacc[i][2]=0.f; sacc[i][3]=0.f; }
        #pragma unroll
        for (int ks = 0; ks < 8; ks++) {
            const float* ap = Qs + r0*A_QS_STRIDE + ks*8 + tig;
            unsigned a0 = __float_as_uint(ap[0]);
            unsigned a1 = __float_as_uint(ap[8*A_QS_STRIDE]);
            unsigned a2 = __float_as_uint(ap[4]);
            unsigned a3 = __float_as_uint(ap[8*A_QS_STRIDE + 4]);
            #pragma unroll
            for (int nt = 0; nt < 8; nt++) {
                const float* bp = ksb + (nt*8 + gid)*A_KS_STRIDE + ks*8 + tig;
                mma_tf32(sacc[nt][0], sacc[nt][1], sacc[nt][2], sacc[nt][3],
                         a0, a1, a2, a3,
                         __float_as_uint(bp[0]), __float_as_uint(bp[4]));
            }
        }

        // sigmoid * coulomb -> Ss (warp-private rows)
        #pragma unroll
        for (int nt = 0; nt < 8; nt++) {
            int sc = nt*8 + 2*tig;
            float* sp = Ss + r0*A_SS_STRIDE + sc;
            sp[0]                 = cvt_tf32(sigmoid_fast(sacc[nt][0]) * creg0[nt].x);
            sp[1]                 = cvt_tf32(sigmoid_fast(sacc[nt][1]) * creg0[nt].y);
            sp[8*A_SS_STRIDE]     = cvt_tf32(sigmoid_fast(sacc[nt][2]) * creg1[nt].x);
            sp[8*A_SS_STRIDE + 1] = cvt_tf32(sigmoid_fast(sacc[nt][3]) * creg1[nt].y);
        }
        __syncwarp();

        // Y += S @ V
        #pragma unroll
        for (int ks = 0; ks < 8; ks++) {
            const float* ap = Ss + r0*A_SS_STRIDE + ks*8 + tig;
            unsigned a0 = __float_as_uint(ap[0]);
            unsigned a1 = __float_as_uint(ap[8*A_SS_STRIDE]);
            unsigned a2 = __float_as_uint(ap[4]);
            unsigned a3 = __float_as_uint(ap[8*A_SS_STRIDE + 4]);
            #pragma unroll
            for (int nt = 0; nt < 8; nt++) {
                const float* bp = vsb + (ks*8 + tig)*A_VS_STRIDE + nt*8 + gid;
                mma_tf32(yacc[nt][0], yacc[nt][1], yacc[nt][2], yacc[nt][3],
                         a0, a1, a2, a3,
                         __float_as_uint(bp[0]), __float_as_uint(bp[4*A_VS_STRIDE]));
            }
        }
    }

    // store Y (fp32, feeds epilogue-add only)
    float* ob = yatt + (size_t)(b*TT + t0 + r0) * CCH + h*DD;
    #pragma unroll
    for (int nt = 0; nt < 8; nt++) {
        int c = nt*8 + 2*tig;
        *(float2*)(ob + c)           = make_float2(yacc[nt][0], yacc[nt][1]);
        *(float2*)(ob + 8*CCH + c)   = make_float2(yacc[nt][2], yacc[nt][3]);
    }
}

// ---------------- launch ----------------
#define G_SMEM_128 ((2*128*36 + 2*32*136)*4)   // 56832 B
#define G_SMEM_64  ((2*128*36 + 2*32*72 )*4)   // 55296 B (BM=128, BN=64)

extern "C" void kernel_launch(void* const* d_in, const int* in_sizes, int n_in,
                              void* d_out, int out_size)
{
    const float* x      = (const float*)d_in[0];
    const float* coul   = (const float*)d_in[2];
    const float* ln1g   = (const float*)d_in[3];
    const float* ln1b   = (const float*)d_in[4];
    const float* w_attn = (const float*)d_in[5];
    const float* b_attn = (const float*)d_in[6];
    const float* w_self = (const float*)d_in[7];
    const float* b_self = (const float*)d_in[8];
    const float* w_proj = (const float*)d_in[9];
    const float* b_proj = (const float*)d_in[10];
    const float* ln2g   = (const float*)d_in[11];
    const float* ln2b   = (const float*)d_in[12];
    const float* w_fc   = (const float*)d_in[13];
    const float* b_fc   = (const float*)d_in[14];
    const float* w_fcp  = (const float*)d_in[15];
    const float* b_fcp  = (const float*)d_in[16];
    float* out = (float*)d_out;

    float *h, *qkvp, *attp, *yp, *y2p, *h2p, *fcp;
    float *wattn, *wself, *wproj, *wfc, *wfcp;
    cudaGetSymbolAddress((void**)&h,    g_h);
    cudaGetSymbolAddress((void**)&qkvp, g_qkv);
    cudaGetSymbolAddress((void**)&attp, g_att);
    cudaGetSymbolAddress((void**)&yp,   g_y);
    cudaGetSymbolAddress((void**)&y2p,  g_y2);
    cudaGetSymbolAddress((void**)&h2p,  g_h2);
    cudaGetSymbolAddress((void**)&fcp,  g_fc);
    cudaGetSymbolAddress((void**)&wattn, g_wattn);
    cudaGetSymbolAddress((void**)&wself, g_wself);
    cudaGetSymbolAddress((void**)&wproj, g_wproj);
    cudaGetSymbolAddress((void**)&wfc,   g_wfc);
    cudaGetSymbolAddress((void**)&wfcp,  g_wfcp);

    // same attribute-set pattern that ran successfully in R3
    cudaFuncSetAttribute((const void*)gemm_tf32<128,128,256,false,false,true>, cudaFuncAttributeMaxDynamicSharedMemorySize, G_SMEM_128);
    cudaFuncSetAttribute((const void*)gemm_tf32<128,128,256,false,true,true>,  cudaFuncAttributeMaxDynamicSharedMemorySize, G_SMEM_128);
    cudaFuncSetAttribute((const void*)gemm_tf32<128,64,128,true,false,true>,   cudaFuncAttributeMaxDynamicSharedMemorySize, G_SMEM_64);
    cudaFuncSetAttribute((const void*)gemm_tf32<128,64,128,false,false,false>, cudaFuncAttributeMaxDynamicSharedMemorySize, G_SMEM_64);
    cudaFuncSetAttribute(attn_tf32, cudaFuncAttributeMaxDynamicSharedMemorySize, A_SMEM);

    // 0) pre-round weights to tf32
    cvt4_kernel<<<(CCH*C3/4 + 255)/256,   256>>>((const float4*)w_attn, (float4*)wattn, CCH*C3/4);
    cvt4_kernel<<<(CCH*CCH/4 + 255)/256,  256>>>((const float4*)w_self, (float4*)wself, CCH*CCH/4);
    cvt4_kernel<<<(CCH*CCH/4 + 255)/256,  256>>>((const float4*)w_proj, (float4*)wproj, CCH*CCH/4);
    cvt4_kernel<<<(CCH*4*CCH/4 + 255)/256,256>>>((const float4*)w_fc,   (float4*)wfc,   CCH*4*CCH/4);
    cvt4_kernel<<<(4*CCH*CCH/4 + 255)/256,256>>>((const float4*)w_fcp,  (float4*)wfcp,  4*CCH*CCH/4);

    // 1) h = LN1(x)   (rounded)
    ln_kernel<<<NROWS, 128>>>(x, ln1g, ln1b, h);
    // 2) qkv = h @ w_attn + b_attn   (rounded out)
    gemm_tf32<128,128,256,false,false,true><<<dim3(12,32), 256, G_SMEM_128>>>(h, wattn, b_attn, nullptr, qkvp, NROWS, C3, CCH);
    // 3) fused sigmoid-attention
    attn_tf32<<<dim3(BB*HH, TT/128), 256, A_SMEM>>>(qkvp, coul, attp);
    // 4) y = att + h @ w_self + b_self   (rounded out -> proj A)
    gemm_tf32<128,64,128,true,false,true><<<dim3(8,32), 128, G_SMEM_64>>>(h, wself, b_self, attp, yp, NROWS, CCH, CCH);
    // 5) y2 = y @ w_proj + b_proj   (fp32 out -> LN2)
    gemm_tf32<128,64,128,false,false,false><<<dim3(8,32), 128, G_SMEM_64>>>(yp, wproj, b_proj, nullptr, y2p, NROWS, CCH, CCH);
    // 6) h2 = LN2(y2)   (rounded)
    ln_kernel<<<NROWS, 128>>>(y2p, ln2g, ln2b, h2p);
    // 7) fc = gelu(h2 @ w_fc + b_fc)   (rounded out)
    gemm_tf32<128,128,256,false,true,true><<<dim3(16,32), 256, G_SMEM_128>>>(h2p, wfc, b_fc, nullptr, fcp, NROWS, 4*CCH, CCH);
    // 8) out = fc @ w_fc_proj + b_fc_proj   (fp32 out)
    gemm_tf32<128,64,128,false,false,false><<<dim3(8,32), 128, G_SMEM_64>>>(fcp, wfcp, b_fcp, nullptr, out, NROWS, CCH, 4*CCH);
}

// round 7
// speedup vs baseline: 1.0930x; 1.0276x over previous
#include <cuda_runtime.h>
#include <math.h>

// Problem constants
#define BB 2
#define TT 2048
#define CCH 512
#define HH 8
#define DD 64
#define NROWS (BB*TT)   // 4096
#define C3 (3*CCH)      // 1536

// ---------------- scratch ----------------
__device__ float g_h  [NROWS*CCH];
__device__ float g_qkv[NROWS*C3];
__device__ float g_att[NROWS*CCH];
__device__ float g_y  [NROWS*CCH];
__device__ float g_y2 [NROWS*CCH];
__device__ float g_h2 [NROWS*CCH];
__device__ float g_fc [NROWS*4*CCH];
// pre-rounded (tf32) weights
__device__ float g_wattn[CCH*C3];
__device__ float g_wself[CCH*CCH];
__device__ float g_wproj[CCH*CCH];
__device__ float g_wfc  [CCH*4*CCH];
__device__ float g_wfcp [4*CCH*CCH];

// ---------------- helpers ----------------
__device__ __forceinline__ float cvt_tf32(float x) {
    unsigned u; asm("cvt.rna.tf32.f32 %0, %1;" : "=r"(u) : "f"(x));
    return __uint_as_float(u);
}

__device__ __forceinline__ void mma_tf32(float& c0, float& c1, float& c2, float& c3,
                                         unsigned a0, unsigned a1, unsigned a2, unsigned a3,
                                         unsigned b0, unsigned b1) {
    asm volatile("mma.sync.aligned.m16n8k8.row.col.f32.tf32.tf32.f32 "
                 "{%0,%1,%2,%3}, {%4,%5,%6,%7}, {%8,%9}, {%0,%1,%2,%3};"
                 : "+f"(c0), "+f"(c1), "+f"(c2), "+f"(c3)
                 : "r"(a0), "r"(a1), "r"(a2), "r"(a3), "r"(b0), "r"(b1));
}

__device__ __forceinline__ void cp16(float* smem_dst, const float* g_src) {
    unsigned s = (unsigned)__cvta_generic_to_shared(smem_dst);
    asm volatile("cp.async.cg.shared.global [%0], [%1], 16;" :: "r"(s), "l"(g_src));
}
__device__ __forceinline__ void cp_commit() {
    asm volatile("cp.async.commit_group;" ::: "memory");
}
__device__ __forceinline__ void cp_wait0() {
    asm volatile("cp.async.wait_group 0;" ::: "memory");
}

// sigmoid via MUFU: 2 SFU ops on an otherwise-idle pipe, concurrent with tensor.
// ex2/rcp approx rel-err ~2^-21 (better than the old degree-6 polynomial).
__device__ __forceinline__ float sigmoid_mufu(float x) {
    float e;
    asm("ex2.approx.f32 %0, %1;" : "=f"(e) : "f"(x * -1.4426950408889634f));
    float r;
    asm("rcp.approx.f32 %0, %1;" : "=f"(r) : "f"(1.0f + e));
    return r;
}

// ---------------- fused weight pre-round (single launch) ----------------
// segments (float4 counts): wattn 196608 | wself 65536 | wproj 65536 | wfc 262144 | wfcp 262144
__global__ __launch_bounds__(256) void cvt_all(
    const float4* __restrict__ w0, float4* __restrict__ o0,
    const float4* __restrict__ w1, float4* __restrict__ o1,
    const float4* __restrict__ w2, float4* __restrict__ o2,
    const float4* __restrict__ w3, float4* __restrict__ o3,
    const float4* __restrict__ w4, float4* __restrict__ o4)
{
    int i = blockIdx.x * 256 + threadIdx.x;
    const float4* src; float4* dst; int j;
    if      (i < 196608) { src = w0; dst = o0; j = i; }
    else if (i < 262144) { src = w1; dst = o1; j = i - 196608; }
    else if (i < 327680) { src = w2; dst = o2; j = i - 262144; }
    else if (i < 589824) { src = w3; dst = o3; j = i - 327680; }
    else                 { src = w4; dst = o4; j = i - 589824; }
    float4 v = src[j];
    v.x = cvt_tf32(v.x); v.y = cvt_tf32(v.y);
    v.z = cvt_tf32(v.z); v.w = cvt_tf32(v.w);
    dst[j] = v;
}

// ---------------- LayerNorm (output rounded to tf32: feeds MMA A) ----------------
__global__ __launch_bounds__(128) void ln_kernel(const float* __restrict__ x,
                                                 const float* __restrict__ g,
                                                 const float* __restrict__ bta,
                                                 float* __restrict__ out)
{
    int row = blockIdx.x;
    int t = threadIdx.x;
    const float4* xr = (const float4*)(x + (size_t)row * CCH);
    float4 v = xr[t];
    float s  = v.x + v.y + v.z + v.w;
    float s2 = v.x*v.x + v.y*v.y + v.z*v.z + v.w*v.w;
    #pragma unroll
    for (int o = 16; o; o >>= 1) {
        s  += __shfl_xor_sync(0xffffffffu, s,  o);
        s2 += __shfl_xor_sync(0xffffffffu, s2, o);
    }
    __shared__ float ss[4], ss2[4];
    int w = t >> 5, l = t & 31;
    if (l == 0) { ss[w] = s; ss2[w] = s2; }
    __syncthreads();
    s  = ss[0]  + ss[1]  + ss[2]  + ss[3];
    s2 = ss2[0] + ss2[1] + ss2[2] + ss2[3];
    float m   = s  * (1.0f/512.0f);
    float var = s2 * (1.0f/512.0f) - m*m;
    float r   = rsqrtf(var + 1e-5f);
    float4 gv = ((const float4*)g)[t];
    float4 bv = ((const float4*)bta)[t];
    float4 o4;
    o4.x = cvt_tf32((v.x - m) * r * gv.x + bv.x);
    o4.y = cvt_tf32((v.y - m) * r * gv.y + bv.y);
    o4.z = cvt_tf32((v.z - m) * r * gv.z + bv.z);
    o4.w = cvt_tf32((v.w - m) * r * gv.w + bv.w);
    ((float4*)(out + (size_t)row * CCH))[t] = o4;
}

// ---------------- TF32 GEMM: BM=128 BN=64 BK=32, 128 thr, warp 64x32 (MT=4,NT=4) ----------------
// cp.async K-tile double-buffer + EXPLICIT ks-level fragment double-buffer
// (load ks+1 frags before issuing ks MMAs -> hide 29-cyc LDS latency).
#define G_AS_STRIDE 36
#define G_BS_STRIDE 72
#define G_AS_SZ (128*G_AS_STRIDE)
#define G_BS_SZ (32*G_BS_STRIDE)
#define G_SMEM ((2*G_AS_SZ + 2*G_BS_SZ)*4)   // 55296 B

template<bool HAS_ADD, bool GELU_EPI, bool ROUND_OUT>
__global__ __launch_bounds__(128, 2) void gemm_tf32(
    const float* __restrict__ A, const float* __restrict__ W,
    const float* __restrict__ bias, const float* __restrict__ addm,
    float* __restrict__ Cmat, int M, int N, int K)
{
    extern __shared__ float sh[];
    float* As = sh;
    float* Bs = sh + 2*G_AS_SZ;

    const int tid  = threadIdx.x;
    const int warp = tid >> 5, lane = tid & 31;
    const int gid  = lane >> 2, tig = lane & 3;
    const int wm   = (warp >> 1) * 64;     // warps 2x2
    const int wn   = (warp & 1) * 32;
    const int bm   = blockIdx.y * 128, bn = blockIdx.x * 64;

    const int ar = tid >> 3, ac = (tid & 7) * 4;    // A: rows ar + i*16 (8 iters)
    const int br = tid >> 4, bc = (tid & 15) * 4;   // B: rows br + i*8  (4 iters)

    const float* Ag = A + (size_t)bm * K;
    const float* Wg = W + bn;

    float acc[4][4][4] = {};
    const int nk = K >> 5;

    // stage 0
    #pragma unroll
    for (int i = 0; i < 8; i++)
        cp16(As + (ar + i*16)*G_AS_STRIDE + ac, Ag + (size_t)(ar + i*16) * K + ac);
    #pragma unroll
    for (int i = 0; i < 4; i++)
        cp16(Bs + (br + i*8)*G_BS_STRIDE + bc, Wg + (size_t)(br + i*8) * N + bc);
    cp_commit();

    for (int kt = 0; kt < nk; kt++) {
        cp_wait0();
        __syncthreads();
        if (kt + 1 < nk) {
            int k0 = (kt + 1) << 5;
            float* asn = As + ((kt + 1) & 1) * G_AS_SZ;
            float* bsn = Bs + ((kt + 1) & 1) * G_BS_SZ;
            #pragma unroll
            for (int i = 0; i < 8; i++)
                cp16(asn + (ar + i*16)*G_AS_STRIDE + ac, Ag + (size_t)(ar + i*16) * K + k0 + ac);
            #pragma unroll
            for (int i = 0; i < 4; i++)
                cp16(bsn + (br + i*8)*G_BS_STRIDE + bc, Wg + (size_t)(k0 + br + i*8) * N + bc);
            cp_commit();
        }
        const float* as = As + (kt & 1) * G_AS_SZ;
        const float* bs = Bs + (kt & 1) * G_BS_SZ;

        unsigned af[2][4][4], bf[2][4][2];
        // preload ks=0 fragments
        #pragma unroll
        for (int mt = 0; mt < 4; mt++) {
            const float* ap = as + (wm + mt*16 + gid)*G_AS_STRIDE + tig;
            af[0][mt][0] = __float_as_uint(ap[0]);
            af[0][mt][1] = __float_as_uint(ap[8*G_AS_STRIDE]);
            af[0][mt][2] = __float_as_uint(ap[4]);
            af[0][mt][3] = __float_as_uint(ap[8*G_AS_STRIDE + 4]);
        }
        #pragma unroll
        for (int nt = 0; nt < 4; nt++) {
            const float* bp = bs + tig*G_BS_STRIDE + wn + nt*8 + gid;
            bf[0][nt][0] = __float_as_uint(bp[0]);
            bf[0][nt][1] = __float_as_uint(bp[4*G_BS_STRIDE]);
        }
        #pragma unroll
        for (int ks = 0; ks < 4; ks++) {
            const int cur = ks & 1, nxt = cur ^ 1;
            if (ks < 3) {   // prefetch ks+1 fragments BEFORE issuing ks MMAs
                #pragma unroll
                for (int mt = 0; mt < 4; mt++) {
                    const float* ap = as + (wm + mt*16 + gid)*G_AS_STRIDE + (ks+1)*8 + tig;
                    af[nxt][mt][0] = __float_as_uint(ap[0]);
                    af[nxt][mt][1] = __float_as_uint(ap[8*G_AS_STRIDE]);
                    af[nxt][mt][2] = __float_as_uint(ap[4]);
                    af[nxt][mt][3] = __float_as_uint(ap[8*G_AS_STRIDE + 4]);
                }
                #pragma unroll
                for (int nt = 0; nt < 4; nt++) {
                    const float* bp = bs + ((ks+1)*8 + tig)*G_BS_STRIDE + wn + nt*8 + gid;
                    bf[nxt][nt][0] = __float_as_uint(bp[0]);
                    bf[nxt][nt][1] = __float_as_uint(bp[4*G_BS_STRIDE]);
                }
            }
            #pragma unroll
            for (int mt = 0; mt < 4; mt++)
                #pragma unroll
                for (int nt = 0; nt < 4; nt++)
                    mma_tf32(acc[mt][nt][0], acc[mt][nt][1], acc[mt][nt][2], acc[mt][nt][3],
                             af[cur][mt][0], af[cur][mt][1], af[cur][mt][2], af[cur][mt][3],
                             bf[cur][nt][0], bf[cur][nt][1]);
        }
    }

    // epilogue
    #pragma unroll
    for (int mt = 0; mt < 4; mt++) {
        int r0 = bm + wm + mt*16 + gid;
        #pragma unroll
        for (int nt = 0; nt < 4; nt++) {
            int c0 = bn + wn + nt*8 + 2*tig;
            float2 bv = *(const float2*)(bias + c0);
            float v0 = acc[mt][nt][0] + bv.x;
            float v1 = acc[mt][nt][1] + bv.y;
            float v2 = acc[mt][nt][2] + bv.x;
            float v3 = acc[mt][nt][3] + bv.y;
            size_t o0 = (size_t)r0 * N + c0;
            size_t o1 = (size_t)(r0 + 8) * N + c0;
            if (HAS_ADD) {
                float2 d0 = *(const float2*)(addm + o0);
                float2 d1 = *(const float2*)(addm + o1);
                v0 += d0.x; v1 += d0.y; v2 += d1.x; v3 += d1.y;
            }
            if (GELU_EPI) {
                v0 = 0.5f * v0 * (1.0f + erff(v0 * 0.70710678118654752f));
                v1 = 0.5f * v1 * (1.0f + erff(v1 * 0.70710678118654752f));
                v2 = 0.5f * v2 * (1.0f + erff(v2 * 0.70710678118654752f));
                v3 = 0.5f * v3 * (1.0f + erff(v3 * 0.70710678118654752f));
            }
            if (ROUND_OUT) {
                v0 = cvt_tf32(v0); v1 = cvt_tf32(v1);
                v2 = cvt_tf32(v2); v3 = cvt_tf32(v3);
            }
            *(float2*)(Cmat + o0) = make_float2(v0, v1);
            *(float2*)(Cmat + o1) = make_float2(v2, v3);
        }
    }
}

// ---------------- TF32 tensor-core attention (MUFU sigmoid) ----------------
#define A_QS_STRIDE 68
#define A_KS_STRIDE 68
#define A_VS_STRIDE 72
#define A_SS_STRIDE 68
#define A_KS_SZ (64*A_KS_STRIDE)
#define A_VS_SZ (64*A_VS_STRIDE)
#define A_SMEM ((128*A_QS_STRIDE + 2*A_KS_SZ + 2*A_VS_SZ + 128*A_SS_STRIDE)*4)

__global__ __launch_bounds__(256) void attn_tf32(const float* __restrict__ qkv,
                                                 const float* __restrict__ coul,
                                                 float* __restrict__ yatt)
{
    extern __shared__ float sh[];
    float* Qs = sh;
    float* Ks = Qs + 128*A_QS_STRIDE;
    float* Vs = Ks + 2*A_KS_SZ;
    float* Ss = Vs + 2*A_VS_SZ;

    int bh = blockIdx.x;               // heads fastest -> coulomb shared in L2
    int b = bh >> 3, h = bh & 7;
    int t0 = blockIdx.y * 128;
    int tid = threadIdx.x, warp = tid >> 5, lane = tid & 31;
    int gid = lane >> 2, tig = lane & 3;

    const int lr = tid >> 4, lc = (tid & 15) * 4;

    // load Q (x 1/8 exact; values pre-rounded tf32)
    const float* qb = qkv + (size_t)(b*TT + t0) * C3 + h*DD;
    #pragma unroll
    for (int i = 0; i < 8; i++) {
        float4 v = *(const float4*)(qb + (size_t)(lr + i*16) * C3 + lc);
        float* p = Qs + (lr + i*16)*A_QS_STRIDE + lc;
        p[0]=v.x*0.125f; p[1]=v.y*0.125f; p[2]=v.z*0.125f; p[3]=v.w*0.125f;
    }

    float yacc[8][4];
    #pragma unroll
    for (int i = 0; i < 8; i++) { yacc[i][0]=0.f; yacc[i][1]=0.f; yacc[i][2]=0.f; yacc[i][3]=0.f; }

    const float* cb = coul + (size_t)b * TT * TT;
    const int r0 = warp*16 + gid;

    const float* kbase = qkv + (size_t)(b*TT) * C3 + CCH + h*DD;

    float4 kreg[4], vreg[4];
    #pragma unroll
    for (int i = 0; i < 4; i++) {
        const float* kb = kbase + (size_t)(lr + i*16) * C3 + lc;
        kreg[i] = *(const float4*)(kb);
        vreg[i] = *(const float4*)(kb + CCH);
    }

    for (int kt = 0; kt < TT/64; kt++) {
        const int s0 = kt * 64;
        float* ksb = Ks + (kt & 1) * A_KS_SZ;
        float* vsb = Vs + (kt & 1) * A_VS_SZ;
        #pragma unroll
        for (int i = 0; i < 4; i++) {
            float* pk = ksb + (lr + i*16)*A_KS_STRIDE + lc;
            pk[0]=kreg[i].x; pk[1]=kreg[i].y; pk[2]=kreg[i].z; pk[3]=kreg[i].w;
            float* pv = vsb + (lr + i*16)*A_VS_STRIDE + lc;
            pv[0]=vreg[i].x; pv[1]=vreg[i].y; pv[2]=vreg[i].z; pv[3]=vreg[i].w;
        }
        __syncthreads();

        // coulomb prefetch for this tile
        float2 creg0[8], creg1[8];
        #pragma unroll
        for (int nt = 0; nt < 8; nt++) {
            int sc = s0 + nt*8 + 2*tig;
            creg0[nt] = *(const float2*)(cb + (size_t)(t0 + r0)     * TT + sc);
            creg1[nt] = *(const float2*)(cb + (size_t)(t0 + r0 + 8) * TT + sc);
        }
        // next K/V tile prefetch
        if (kt + 1 < TT/64) {
            #pragma unroll
            for (int i = 0; i < 4; i++) {
                const float* kb = kbase + (size_t)(s0 + 64 + lr + i*16) * C3 + lc;
                kreg[i] = *(const float4*)(kb);
                vreg[i] = *(const float4*)(kb + CCH);
            }
        }

        // S = Q @ K^T
        float sacc[8][4];
        #pragma unroll
        for (int i = 0; i < 8; i++) { sacc[i][0]=0.f; sacc[i][1]=0.f; sacc[i][2]=0.f; sacc[i][3]=0.f; }
        #pragma unroll
        for (int ks = 0; ks < 8; ks++) {
            const float* ap = Qs + r0*A_QS_STRIDE + ks*8 + tig;
            unsigned a0 = __float_as_uint(ap[0]);
            unsigned a1 = __float_as_uint(ap[8*A_QS_STRIDE]);
            unsigned a2 = __float_as_uint(ap[4]);
            unsigned a3 = __float_as_uint(ap[8*A_QS_STRIDE + 4]);
            #pragma unroll
            for (int nt = 0; nt < 8; nt++) {
                const float* bp = ksb + (nt*8 + gid)*A_KS_STRIDE + ks*8 + tig;
                mma_tf32(sacc[nt][0], sacc[nt][1], sacc[nt][2], sacc[nt][3],
                         a0, a1, a2, a3,
                         __float_as_uint(bp[0]), __float_as_uint(bp[4]));
            }
        }

        // sigmoid(MUFU) * coulomb -> Ss (warp-private rows)
        #pragma unroll
        for (int nt = 0; nt < 8; nt++) {
            int sc = nt*8 + 2*tig;
            float* sp = Ss + r0*A_SS_STRIDE + sc;
            sp[0]                 = cvt_tf32(sigmoid_mufu(sacc[nt][0]) * creg0[nt].x);
            sp[1]                 = cvt_tf32(sigmoid_mufu(sacc[nt][1]) * creg0[nt].y);
            sp[8*A_SS_STRIDE]     = cvt_tf32(sigmoid_mufu(sacc[nt][2]) * creg1[nt].x);
            sp[8*A_SS_STRIDE + 1] = cvt_tf32(sigmoid_mufu(sacc[nt][3]) * creg1[nt].y);
        }
        __syncwarp();

        // Y += S @ V
        #pragma unroll
        for (int ks = 0; ks < 8; ks++) {
            const float* ap = Ss + r0*A_SS_STRIDE + ks*8 + tig;
            unsigned a0 = __float_as_uint(ap[0]);
            unsigned a1 = __float_as_uint(ap[8*A_SS_STRIDE]);
            unsigned a2 = __float_as_uint(ap[4]);
            unsigned a3 = __float_as_uint(ap[8*A_SS_STRIDE + 4]);
            #pragma unroll
            for (int nt = 0; nt < 8; nt++) {
                const float* bp = vsb + (ks*8 + tig)*A_VS_STRIDE + nt*8 + gid;
                mma_tf32(yacc[nt][0], yacc[nt][1], yacc[nt][2], yacc[nt][3],
                         a0, a1, a2, a3,
                         __float_as_uint(bp[0]), __float_as_uint(bp[4*A_VS_STRIDE]));
            }
        }
    }

    // store Y (fp32, feeds epilogue-add only)
    float* ob = yatt + (size_t)(b*TT + t0 + r0) * CCH + h*DD;
    #pragma unroll
    for (int nt = 0; nt < 8; nt++) {
        int c = nt*8 + 2*tig;
        *(float2*)(ob + c)           = make_float2(yacc[nt][0], yacc[nt][1]);
        *(float2*)(ob + 8*CCH + c)   = make_float2(yacc[nt][2], yacc[nt][3]);
    }
}

// ---------------- launch ----------------
extern "C" void kernel_launch(void* const* d_in, const int* in_sizes, int n_in,
                              void* d_out, int out_size)
{
    const float* x      = (const float*)d_in[0];
    const float* coul   = (const float*)d_in[2];
    const float* ln1g   = (const float*)d_in[3];
    const float* ln1b   = (const float*)d_in[4];
    const float* w_attn = (const float*)d_in[5];
    const float* b_attn = (const float*)d_in[6];
    const float* w_self = (const float*)d_in[7];
    const float* b_self = (const float*)d_in[8];
    const float* w_proj = (const float*)d_in[9];
    const float* b_proj = (const float*)d_in[10];
    const float* ln2g   = (const float*)d_in[11];
    const float* ln2b   = (const float*)d_in[12];
    const float* w_fc   = (const float*)d_in[13];
    const float* b_fc   = (const float*)d_in[14];
    const float* w_fcp  = (const float*)d_in[15];
    const float* b_fcp  = (const float*)d_in[16];
    float* out = (float*)d_out;

    float *h, *qkvp, *attp, *yp, *y2p, *h2p, *fcp;
    float *wattn, *wself, *wproj, *wfc, *wfcp;
    cudaGetSymbolAddress((void**)&h,    g_h);
    cudaGetSymbolAddress((void**)&qkvp, g_qkv);
    cudaGetSymbolAddress((void**)&attp, g_att);
    cudaGetSymbolAddress((void**)&yp,   g_y);
    cudaGetSymbolAddress((void**)&y2p,  g_y2);
    cudaGetSymbolAddress((void**)&h2p,  g_h2);
    cudaGetSymbolAddress((void**)&fcp,  g_fc);
    cudaGetSymbolAddress((void**)&wattn, g_wattn);
    cudaGetSymbolAddress((void**)&wself, g_wself);
    cudaGetSymbolAddress((void**)&wproj, g_wproj);
    cudaGetSymbolAddress((void**)&wfc,   g_wfc);
    cudaGetSymbolAddress((void**)&wfcp,  g_wfcp);

    cudaFuncSetAttribute((const void*)gemm_tf32<false,false,true>,  cudaFuncAttributeMaxDynamicSharedMemorySize, G_SMEM);
    cudaFuncSetAttribute((const void*)gemm_tf32<false,true,true>,   cudaFuncAttributeMaxDynamicSharedMemorySize, G_SMEM);
    cudaFuncSetAttribute((const void*)gemm_tf32<true,false,true>,   cudaFuncAttributeMaxDynamicSharedMemorySize, G_SMEM);
    cudaFuncSetAttribute((const void*)gemm_tf32<false,false,false>, cudaFuncAttributeMaxDynamicSharedMemorySize, G_SMEM);
    cudaFuncSetAttribute(attn_tf32, cudaFuncAttributeMaxDynamicSharedMemorySize, A_SMEM);

    // 0) pre-round weights to tf32 (single fused launch, 851968 float4 = 3328 blocks)
    cvt_all<<<3328, 256>>>((const float4*)w_attn, (float4*)wattn,
                           (const float4*)w_self, (float4*)wself,
                           (const float4*)w_proj, (float4*)wproj,
                           (const float4*)w_fc,   (float4*)wfc,
                           (const float4*)w_fcp,  (float4*)wfcp);

    // 1) h = LN1(x)   (rounded)
    ln_kernel<<<NROWS, 128>>>(x, ln1g, ln1b, h);
    // 2) qkv = h @ w_attn + b_attn   [4096x1536] grid (24,32)=768
    gemm_tf32<false,false,true><<<dim3(24,32), 128, G_SMEM>>>(h, wattn, b_attn, nullptr, qkvp, NROWS, C3, CCH);
    // 3) fused sigmoid-attention
    attn_tf32<<<dim3(BB*HH, TT/128), 256, A_SMEM>>>(qkvp, coul, attp);
    // 4) y = att + h @ w_self + b_self   [4096x512] grid (8,32)=256
    gemm_tf32<true,false,true><<<dim3(8,32), 128, G_SMEM>>>(h, wself, b_self, attp, yp, NROWS, CCH, CCH);
    // 5) y2 = y @ w_proj + b_proj   [4096x512]
    gemm_tf32<false,false,false><<<dim3(8,32), 128, G_SMEM>>>(yp, wproj, b_proj, nullptr, y2p, NROWS, CCH, CCH);
    // 6) h2 = LN2(y2)   (rounded)
    ln_kernel<<<NROWS, 128>>>(y2p, ln2g, ln2b, h2p);
    // 7) fc = gelu(h2 @ w_fc + b_fc)   [4096x2048] grid (32,32)=1024
    gemm_tf32<false,true,true><<<dim3(32,32), 128, G_SMEM>>>(h2p, wfc, b_fc, nullptr, fcp, NROWS, 4*CCH, CCH);
    // 8) out = fc @ w_fc_proj + b_fc_proj   [4096x512], K=2048
    gemm_tf32<false,false,false><<<dim3(8,32), 128, G_SMEM>>>(fcp, wfcp, b_fcp, nullptr, out, NROWS, CCH, 4*CCH);
}

// round 8
// speedup vs baseline: 1.2006x; 1.0984x over previous
#include <cuda_runtime.h>
#include <math.h>

// Problem constants
#define BB 2
#define TT 2048
#define CCH 512
#define HH 8
#define DD 64
#define NROWS (BB*TT)   // 4096
#define C3 (3*CCH)      // 1536

// ---------------- scratch ----------------
__device__ float g_h  [NROWS*CCH];
__device__ float g_qkv[NROWS*C3];
__device__ float g_att[NROWS*CCH];
__device__ float g_y  [NROWS*CCH];
__device__ float g_y2 [NROWS*CCH];
__device__ float g_h2 [NROWS*CCH];
__device__ float g_fc [NROWS*4*CCH];
// pre-rounded (tf32) weights
__device__ float g_wattn[CCH*C3];
__device__ float g_wself[CCH*CCH];
__device__ float g_wproj[CCH*CCH];
__device__ float g_wfc  [CCH*4*CCH];
__device__ float g_wfcp [4*CCH*CCH];

// ---------------- helpers ----------------
__device__ __forceinline__ float cvt_tf32(float x) {
    unsigned u; asm("cvt.rna.tf32.f32 %0, %1;" : "=r"(u) : "f"(x));
    return __uint_as_float(u);
}

__device__ __forceinline__ void mma_tf32(float& c0, float& c1, float& c2, float& c3,
                                         unsigned a0, unsigned a1, unsigned a2, unsigned a3,
                                         unsigned b0, unsigned b1) {
    asm volatile("mma.sync.aligned.m16n8k8.row.col.f32.tf32.tf32.f32 "
                 "{%0,%1,%2,%3}, {%4,%5,%6,%7}, {%8,%9}, {%0,%1,%2,%3};"
                 : "+f"(c0), "+f"(c1), "+f"(c2), "+f"(c3)
                 : "r"(a0), "r"(a1), "r"(a2), "r"(a3), "r"(b0), "r"(b1));
}

__device__ __forceinline__ void cp16(float* smem_dst, const float* g_src) {
    unsigned s = (unsigned)__cvta_generic_to_shared(smem_dst);
    asm volatile("cp.async.cg.shared.global [%0], [%1], 16;" :: "r"(s), "l"(g_src));
}
__device__ __forceinline__ void cp_commit() {
    asm volatile("cp.async.commit_group;" ::: "memory");
}
__device__ __forceinline__ void cp_wait0() {
    asm volatile("cp.async.wait_group 0;" ::: "memory");
}

// sigmoid via MUFU (2 SFU ops, concurrent with tensor pipe)
__device__ __forceinline__ float sigmoid_mufu(float x) {
    float e;
    asm("ex2.approx.f32 %0, %1;" : "=f"(e) : "f"(x * -1.4426950408889634f));
    float r;
    asm("rcp.approx.f32 %0, %1;" : "=f"(r) : "f"(1.0f + e));
    return r;
}

// ---------------- fused weight pre-round (single launch) ----------------
__global__ __launch_bounds__(256) void cvt_all(
    const float4* __restrict__ w0, float4* __restrict__ o0,
    const float4* __restrict__ w1, float4* __restrict__ o1,
    const float4* __restrict__ w2, float4* __restrict__ o2,
    const float4* __restrict__ w3, float4* __restrict__ o3,
    const float4* __restrict__ w4, float4* __restrict__ o4)
{
    int i = blockIdx.x * 256 + threadIdx.x;
    const float4* src; float4* dst; int j;
    if      (i < 196608) { src = w0; dst = o0; j = i; }
    else if (i < 262144) { src = w1; dst = o1; j = i - 196608; }
    else if (i < 327680) { src = w2; dst = o2; j = i - 262144; }
    else if (i < 589824) { src = w3; dst = o3; j = i - 327680; }
    else                 { src = w4; dst = o4; j = i - 589824; }
    float4 v = src[j];
    v.x = cvt_tf32(v.x); v.y = cvt_tf32(v.y);
    v.z = cvt_tf32(v.z); v.w = cvt_tf32(v.w);
    dst[j] = v;
}

// ---------------- LayerNorm (output rounded to tf32: feeds MMA A) ----------------
__global__ __launch_bounds__(128) void ln_kernel(const float* __restrict__ x,
                                                 const float* __restrict__ g,
                                                 const float* __restrict__ bta,
                                                 float* __restrict__ out)
{
    int row = blockIdx.x;
    int t = threadIdx.x;
    const float4* xr = (const float4*)(x + (size_t)row * CCH);
    float4 v = xr[t];
    float s  = v.x + v.y + v.z + v.w;
    float s2 = v.x*v.x + v.y*v.y + v.z*v.z + v.w*v.w;
    #pragma unroll
    for (int o = 16; o; o >>= 1) {
        s  += __shfl_xor_sync(0xffffffffu, s,  o);
        s2 += __shfl_xor_sync(0xffffffffu, s2, o);
    }
    __shared__ float ss[4], ss2[4];
    int w = t >> 5, l = t & 31;
    if (l == 0) { ss[w] = s; ss2[w] = s2; }
    __syncthreads();
    s  = ss[0]  + ss[1]  + ss[2]  + ss[3];
    s2 = ss2[0] + ss2[1] + ss2[2] + ss2[3];
    float m   = s  * (1.0f/512.0f);
    float var = s2 * (1.0f/512.0f) - m*m;
    float r   = rsqrtf(var + 1e-5f);
    float4 gv = ((const float4*)g)[t];
    float4 bv = ((const float4*)bta)[t];
    float4 o4;
    o4.x = cvt_tf32((v.x - m) * r * gv.x + bv.x);
    o4.y = cvt_tf32((v.y - m) * r * gv.y + bv.y);
    o4.z = cvt_tf32((v.z - m) * r * gv.z + bv.z);
    o4.w = cvt_tf32((v.w - m) * r * gv.w + bv.w);
    ((float4*)(out + (size_t)row * CCH))[t] = o4;
}

// ---------------- TF32 GEMM (unchanged from R7) ----------------
#define G_AS_STRIDE 36
#define G_BS_STRIDE 72
#define G_AS_SZ (128*G_AS_STRIDE)
#define G_BS_SZ (32*G_BS_STRIDE)
#define G_SMEM ((2*G_AS_SZ + 2*G_BS_SZ)*4)   // 55296 B

template<bool HAS_ADD, bool GELU_EPI, bool ROUND_OUT>
__global__ __launch_bounds__(128, 2) void gemm_tf32(
    const float* __restrict__ A, const float* __restrict__ W,
    const float* __restrict__ bias, const float* __restrict__ addm,
    float* __restrict__ Cmat, int M, int N, int K)
{
    extern __shared__ float sh[];
    float* As = sh;
    float* Bs = sh + 2*G_AS_SZ;

    const int tid  = threadIdx.x;
    const int warp = tid >> 5, lane = tid & 31;
    const int gid  = lane >> 2, tig = lane & 3;
    const int wm   = (warp >> 1) * 64;
    const int wn   = (warp & 1) * 32;
    const int bm   = blockIdx.y * 128, bn = blockIdx.x * 64;

    const int ar = tid >> 3, ac = (tid & 7) * 4;
    const int br = tid >> 4, bc = (tid & 15) * 4;

    const float* Ag = A + (size_t)bm * K;
    const float* Wg = W + bn;

    float acc[4][4][4] = {};
    const int nk = K >> 5;

    #pragma unroll
    for (int i = 0; i < 8; i++)
        cp16(As + (ar + i*16)*G_AS_STRIDE + ac, Ag + (size_t)(ar + i*16) * K + ac);
    #pragma unroll
    for (int i = 0; i < 4; i++)
        cp16(Bs + (br + i*8)*G_BS_STRIDE + bc, Wg + (size_t)(br + i*8) * N + bc);
    cp_commit();

    for (int kt = 0; kt < nk; kt++) {
        cp_wait0();
        __syncthreads();
        if (kt + 1 < nk) {
            int k0 = (kt + 1) << 5;
            float* asn = As + ((kt + 1) & 1) * G_AS_SZ;
            float* bsn = Bs + ((kt + 1) & 1) * G_BS_SZ;
            #pragma unroll
            for (int i = 0; i < 8; i++)
                cp16(asn + (ar + i*16)*G_AS_STRIDE + ac, Ag + (size_t)(ar + i*16) * K + k0 + ac);
            #pragma unroll
            for (int i = 0; i < 4; i++)
                cp16(bsn + (br + i*8)*G_BS_STRIDE + bc, Wg + (size_t)(k0 + br + i*8) * N + bc);
            cp_commit();
        }
        const float* as = As + (kt & 1) * G_AS_SZ;
        const float* bs = Bs + (kt & 1) * G_BS_SZ;

        unsigned af[2][4][4], bf[2][4][2];
        #pragma unroll
        for (int mt = 0; mt < 4; mt++) {
            const float* ap = as + (wm + mt*16 + gid)*G_AS_STRIDE + tig;
            af[0][mt][0] = __float_as_uint(ap[0]);
            af[0][mt][1] = __float_as_uint(ap[8*G_AS_STRIDE]);
            af[0][mt][2] = __float_as_uint(ap[4]);
            af[0][mt][3] = __float_as_uint(ap[8*G_AS_STRIDE + 4]);
        }
        #pragma unroll
        for (int nt = 0; nt < 4; nt++) {
            const float* bp = bs + tig*G_BS_STRIDE + wn + nt*8 + gid;
            bf[0][nt][0] = __float_as_uint(bp[0]);
            bf[0][nt][1] = __float_as_uint(bp[4*G_BS_STRIDE]);
        }
        #pragma unroll
        for (int ks = 0; ks < 4; ks++) {
            const int cur = ks & 1, nxt = cur ^ 1;
            if (ks < 3) {
                #pragma unroll
                for (int mt = 0; mt < 4; mt++) {
                    const float* ap = as + (wm + mt*16 + gid)*G_AS_STRIDE + (ks+1)*8 + tig;
                    af[nxt][mt][0] = __float_as_uint(ap[0]);
                    af[nxt][mt][1] = __float_as_uint(ap[8*G_AS_STRIDE]);
                    af[nxt][mt][2] = __float_as_uint(ap[4]);
                    af[nxt][mt][3] = __float_as_uint(ap[8*G_AS_STRIDE + 4]);
                }
                #pragma unroll
                for (int nt = 0; nt < 4; nt++) {
                    const float* bp = bs + ((ks+1)*8 + tig)*G_BS_STRIDE + wn + nt*8 + gid;
                    bf[nxt][nt][0] = __float_as_uint(bp[0]);
                    bf[nxt][nt][1] = __float_as_uint(bp[4*G_BS_STRIDE]);
                }
            }
            #pragma unroll
            for (int mt = 0; mt < 4; mt++)
                #pragma unroll
                for (int nt = 0; nt < 4; nt++)
                    mma_tf32(acc[mt][nt][0], acc[mt][nt][1], acc[mt][nt][2], acc[mt][nt][3],
                             af[cur][mt][0], af[cur][mt][1], af[cur][mt][2], af[cur][mt][3],
                             bf[cur][nt][0], bf[cur][nt][1]);
        }
    }

    #pragma unroll
    for (int mt = 0; mt < 4; mt++) {
        int r0 = bm + wm + mt*16 + gid;
        #pragma unroll
        for (int nt = 0; nt < 4; nt++) {
            int c0 = bn + wn + nt*8 + 2*tig;
            float2 bv = *(const float2*)(bias + c0);
            float v0 = acc[mt][nt][0] + bv.x;
            float v1 = acc[mt][nt][1] + bv.y;
            float v2 = acc[mt][nt][2] + bv.x;
            float v3 = acc[mt][nt][3] + bv.y;
            size_t o0 = (size_t)r0 * N + c0;
            size_t o1 = (size_t)(r0 + 8) * N + c0;
            if (HAS_ADD) {
                float2 d0 = *(const float2*)(addm + o0);
                float2 d1 = *(const float2*)(addm + o1);
                v0 += d0.x; v1 += d0.y; v2 += d1.x; v3 += d1.y;
            }
            if (GELU_EPI) {
                v0 = 0.5f * v0 * (1.0f + erff(v0 * 0.70710678118654752f));
                v1 = 0.5f * v1 * (1.0f + erff(v1 * 0.70710678118654752f));
                v2 = 0.5f * v2 * (1.0f + erff(v2 * 0.70710678118654752f));
                v3 = 0.5f * v3 * (1.0f + erff(v3 * 0.70710678118654752f));
            }
            if (ROUND_OUT) {
                v0 = cvt_tf32(v0); v1 = cvt_tf32(v1);
                v2 = cvt_tf32(v2); v3 = cvt_tf32(v3);
            }
            *(float2*)(Cmat + o0) = make_float2(v0, v1);
            *(float2*)(Cmat + o1) = make_float2(v2, v3);
        }
    }
}

// ---------------- attention: 2 CTAs/SM (Q in regs, cp.async K/V, half-tile S) ----------------
#define A_KS_STRIDE 68
#define A_VS_STRIDE 72
#define A_SS_STRIDE 36
#define A_KS_SZ (64*A_KS_STRIDE)      // 4352 floats
#define A_VS_SZ (64*A_VS_STRIDE)      // 4608 floats
#define A_SMEM ((2*A_KS_SZ + 2*A_VS_SZ + 128*A_SS_STRIDE)*4)   // 90112 B

__global__ __launch_bounds__(256, 2) void attn_tf32(const float* __restrict__ qkv,
                                                    const float* __restrict__ coul,
                                                    float* __restrict__ yatt)
{
    extern __shared__ float sh[];
    float* Ks = sh;                       // 2 buffers
    float* Vs = sh + 2*A_KS_SZ;           // 2 buffers
    float* Ss = Vs + 2*A_VS_SZ;           // [128][36], warp-private rows

    const int bh = blockIdx.x;            // heads fastest -> coulomb L2 sharing
    const int b = bh >> 3, h = bh & 7;
    const int t0 = blockIdx.y * 128;
    const int tid = threadIdx.x, warp = tid >> 5, lane = tid & 31;
    const int gid = lane >> 2, tig = lane & 3;
    const int lr = tid >> 4, lc = (tid & 15) * 4;
    const int r0 = warp*16 + gid;

    // Q fragments in registers (warp-private rows; values already tf32, x0.125 exact)
    float qf[8][4];
    {
        const float* q0 = qkv + (size_t)(b*TT + t0 + r0) * C3 + h*DD;
        #pragma unroll
        for (int kd = 0; kd < 8; kd++) {
            qf[kd][0] = q0[kd*8 + tig]            * 0.125f;
            qf[kd][1] = q0[8*C3 + kd*8 + tig]     * 0.125f;
            qf[kd][2] = q0[kd*8 + tig + 4]        * 0.125f;
            qf[kd][3] = q0[8*C3 + kd*8 + tig + 4] * 0.125f;
        }
    }

    float yacc[8][4];
    #pragma unroll
    for (int i = 0; i < 8; i++) { yacc[i][0]=0.f; yacc[i][1]=0.f; yacc[i][2]=0.f; yacc[i][3]=0.f; }

    const float* cb0 = coul + (size_t)b * TT * TT + (size_t)(t0 + r0) * TT;
    const float* cb1 = cb0 + 8 * TT;
    const float* kbase = qkv + (size_t)(b*TT) * C3 + CCH + h*DD;   // K; V at +CCH

    // prologue: cp.async s-tile 0
    #pragma unroll
    for (int i = 0; i < 4; i++) {
        cp16(Ks + (lr + i*16)*A_KS_STRIDE + lc, kbase + (size_t)(lr + i*16) * C3 + lc);
        cp16(Vs + (lr + i*16)*A_VS_STRIDE + lc, kbase + CCH + (size_t)(lr + i*16) * C3 + lc);
    }
    cp_commit();

    for (int kt = 0; kt < TT/64; kt++) {
        cp_wait0();
        __syncthreads();
        if (kt + 1 < TT/64) {
            const float* kn = kbase + (size_t)((kt + 1) * 64) * C3;
            float* kd_ = Ks + ((kt + 1) & 1) * A_KS_SZ;
            float* vd_ = Vs + ((kt + 1) & 1) * A_VS_SZ;
            #pragma unroll
            for (int i = 0; i < 4; i++) {
                cp16(kd_ + (lr + i*16)*A_KS_STRIDE + lc, kn + (size_t)(lr + i*16) * C3 + lc);
                cp16(vd_ + (lr + i*16)*A_VS_STRIDE + lc, kn + CCH + (size_t)(lr + i*16) * C3 + lc);
            }
            cp_commit();
        }
        const float* ksb = Ks + (kt & 1) * A_KS_SZ;
        const float* vsb = Vs + (kt & 1) * A_VS_SZ;
        const int s0 = kt * 64;

        #pragma unroll
        for (int hf = 0; hf < 2; hf++) {
            // coulomb prefetch for this 32-col half (hidden under QK MMAs)
            float2 c0[4], c1[4];
            #pragma unroll
            for (int nt = 0; nt < 4; nt++) {
                int sc = s0 + hf*32 + nt*8 + 2*tig;
                c0[nt] = *(const float2*)(cb0 + sc);
                c1[nt] = *(const float2*)(cb1 + sc);
            }

            // S = Q @ K^T for cols [hf*32, hf*32+32)
            float sacc[4][4];
            #pragma unroll
            for (int i = 0; i < 4; i++) { sacc[i][0]=0.f; sacc[i][1]=0.f; sacc[i][2]=0.f; sacc[i][3]=0.f; }
            #pragma unroll
            for (int kd = 0; kd < 8; kd++) {
                unsigned a0 = __float_as_uint(qf[kd][0]);
                unsigned a1 = __float_as_uint(qf[kd][1]);
                unsigned a2 = __float_as_uint(qf[kd][2]);
                unsigned a3 = __float_as_uint(qf[kd][3]);
                #pragma unroll
                for (int nt = 0; nt < 4; nt++) {
                    const float* bp = ksb + (hf*32 + nt*8 + gid)*A_KS_STRIDE + kd*8 + tig;
                    mma_tf32(sacc[nt][0], sacc[nt][1], sacc[nt][2], sacc[nt][3],
                             a0, a1, a2, a3,
                             __float_as_uint(bp[0]), __float_as_uint(bp[4]));
                }
            }

            // sigmoid(MUFU) * coulomb -> Ss (warp-private rows)
            #pragma unroll
            for (int nt = 0; nt < 4; nt++) {
                float* sp = Ss + r0*A_SS_STRIDE + nt*8 + 2*tig;
                sp[0]                 = cvt_tf32(sigmoid_mufu(sacc[nt][0]) * c0[nt].x);
                sp[1]                 = cvt_tf32(sigmoid_mufu(sacc[nt][1]) * c0[nt].y);
                sp[8*A_SS_STRIDE]     = cvt_tf32(sigmoid_mufu(sacc[nt][2]) * c1[nt].x);
                sp[8*A_SS_STRIDE + 1] = cvt_tf32(sigmoid_mufu(sacc[nt][3]) * c1[nt].y);
            }
            __syncwarp();

            // Y += S_half @ V_half
            #pragma unroll
            for (int ks = 0; ks < 4; ks++) {
                const float* ap = Ss + r0*A_SS_STRIDE + ks*8 + tig;
                unsigned a0 = __float_as_uint(ap[0]);
                unsigned a1 = __float_as_uint(ap[8*A_SS_STRIDE]);
                unsigned a2 = __float_as_uint(ap[4]);
                unsigned a3 = __float_as_uint(ap[8*A_SS_STRIDE + 4]);
                #pragma unroll
                for (int nt = 0; nt < 8; nt++) {
                    const float* bp = vsb + (hf*32 + ks*8 + tig)*A_VS_STRIDE + nt*8 + gid;
                    mma_tf32(yacc[nt][0], yacc[nt][1], yacc[nt][2], yacc[nt][3],
                             a0, a1, a2, a3,
                             __float_as_uint(bp[0]), __float_as_uint(bp[4*A_VS_STRIDE]));
                }
            }
            __syncwarp();   // Ss reused by next half
        }
    }

    // store Y
    float* ob = yatt + (size_t)(b*TT + t0 + r0) * CCH + h*DD;
    #pragma unroll
    for (int nt = 0; nt < 8; nt++) {
        int c = nt*8 + 2*tig;
        *(float2*)(ob + c)           = make_float2(yacc[nt][0], yacc[nt][1]);
        *(float2*)(ob + 8*CCH + c)   = make_float2(yacc[nt][2], yacc[nt][3]);
    }
}

// ---------------- launch ----------------
extern "C" void kernel_launch(void* const* d_in, const int* in_sizes, int n_in,
                              void* d_out, int out_size)
{
    const float* x      = (const float*)d_in[0];
    const float* coul   = (const float*)d_in[2];
    const float* ln1g   = (const float*)d_in[3];
    const float* ln1b   = (const float*)d_in[4];
    const float* w_attn = (const float*)d_in[5];
    const float* b_attn = (const float*)d_in[6];
    const float* w_self = (const float*)d_in[7];
    const float* b_self = (const float*)d_in[8];
    const float* w_proj = (const float*)d_in[9];
    const float* b_proj = (const float*)d_in[10];
    const float* ln2g   = (const float*)d_in[11];
    const float* ln2b   = (const float*)d_in[12];
    const float* w_fc   = (const float*)d_in[13];
    const float* b_fc   = (const float*)d_in[14];
    const float* w_fcp  = (const float*)d_in[15];
    const float* b_fcp  = (const float*)d_in[16];
    float* out = (float*)d_out;

    float *h, *qkvp, *attp, *yp, *y2p, *h2p, *fcp;
    float *wattn, *wself, *wproj, *wfc, *wfcp;
    cudaGetSymbolAddress((void**)&h,    g_h);
    cudaGetSymbolAddress((void**)&qkvp, g_qkv);
    cudaGetSymbolAddress((void**)&attp, g_att);
    cudaGetSymbolAddress((void**)&yp,   g_y);
    cudaGetSymbolAddress((void**)&y2p,  g_y2);
    cudaGetSymbolAddress((void**)&h2p,  g_h2);
    cudaGetSymbolAddress((void**)&fcp,  g_fc);
    cudaGetSymbolAddress((void**)&wattn, g_wattn);
    cudaGetSymbolAddress((void**)&wself, g_wself);
    cudaGetSymbolAddress((void**)&wproj, g_wproj);
    cudaGetSymbolAddress((void**)&wfc,   g_wfc);
    cudaGetSymbolAddress((void**)&wfcp,  g_wfcp);

    cudaFuncSetAttribute((const void*)gemm_tf32<false,false,true>,  cudaFuncAttributeMaxDynamicSharedMemorySize, G_SMEM);
    cudaFuncSetAttribute((const void*)gemm_tf32<false,true,true>,   cudaFuncAttributeMaxDynamicSharedMemorySize, G_SMEM);
    cudaFuncSetAttribute((const void*)gemm_tf32<true,false,true>,   cudaFuncAttributeMaxDynamicSharedMemorySize, G_SMEM);
    cudaFuncSetAttribute((const void*)gemm_tf32<false,false,false>, cudaFuncAttributeMaxDynamicSharedMemorySize, G_SMEM);
    cudaFuncSetAttribute(attn_tf32, cudaFuncAttributeMaxDynamicSharedMemorySize, A_SMEM);

    // 0) pre-round weights to tf32
    cvt_all<<<3328, 256>>>((const float4*)w_attn, (float4*)wattn,
                           (const float4*)w_self, (float4*)wself,
                           (const float4*)w_proj, (float4*)wproj,
                           (const float4*)w_fc,   (float4*)wfc,
                           (const float4*)w_fcp,  (float4*)wfcp);

    // 1) h = LN1(x)
    ln_kernel<<<NROWS, 128>>>(x, ln1g, ln1b, h);
    // 2) qkv = h @ w_attn + b_attn
    gemm_tf32<false,false,true><<<dim3(24,32), 128, G_SMEM>>>(h, wattn, b_attn, nullptr, qkvp, NROWS, C3, CCH);
    // 3) fused sigmoid-attention (2 CTAs/SM -> whole grid in one wave)
    attn_tf32<<<dim3(BB*HH, TT/128), 256, A_SMEM>>>(qkvp, coul, attp);
    // 4) y = att + h @ w_self + b_self
    gemm_tf32<true,false,true><<<dim3(8,32), 128, G_SMEM>>>(h, wself, b_self, attp, yp, NROWS, CCH, CCH);
    // 5) y2 = y @ w_proj + b_proj
    gemm_tf32<false,false,false><<<dim3(8,32), 128, G_SMEM>>>(yp, wproj, b_proj, nullptr, y2p, NROWS, CCH, CCH);
    // 6) h2 = LN2(y2)
    ln_kernel<<<NROWS, 128>>>(y2p, ln2g, ln2b, h2p);
    // 7) fc = gelu(h2 @ w_fc + b_fc)
    gemm_tf32<false,true,true><<<dim3(32,32), 128, G_SMEM>>>(h2p, wfc, b_fc, nullptr, fcp, NROWS, 4*CCH, CCH);
    // 8) out = fc @ w_fc_proj + b_fc_proj
    gemm_tf32<false,false,false><<<dim3(8,32), 128, G_SMEM>>>(fcp, wfcp, b_fcp, nullptr, out, NROWS, CCH, 4*CCH);
}

// round 9
// speedup vs baseline: 1.2192x; 1.0155x over previous
#include <cuda_runtime.h>
#include <math.h>

// Problem constants
#define BB 2
#define TT 2048
#define CCH 512
#define HH 8
#define DD 64
#define NROWS (BB*TT)   // 4096
#define C3 (3*CCH)      // 1536

// ---------------- scratch ----------------
__device__ float g_h   [NROWS*CCH];
__device__ float g_qkv [NROWS*C3];
__device__ float g_att0[NROWS*CCH];   // attention partial (s-half 0)
__device__ float g_att1[NROWS*CCH];   // attention partial (s-half 1)
__device__ float g_y   [NROWS*CCH];
__device__ float g_y2  [NROWS*CCH];
__device__ float g_h2  [NROWS*CCH];
__device__ float g_fc  [NROWS*4*CCH];
// pre-rounded (tf32) weights
__device__ float g_wattn[CCH*C3];
__device__ float g_wself[CCH*CCH];
__device__ float g_wproj[CCH*CCH];
__device__ float g_wfc  [CCH*4*CCH];
__device__ float g_wfcp [4*CCH*CCH];

// ---------------- helpers ----------------
__device__ __forceinline__ float cvt_tf32(float x) {
    unsigned u; asm("cvt.rna.tf32.f32 %0, %1;" : "=r"(u) : "f"(x));
    return __uint_as_float(u);
}

__device__ __forceinline__ void mma_tf32(float& c0, float& c1, float& c2, float& c3,
                                         unsigned a0, unsigned a1, unsigned a2, unsigned a3,
                                         unsigned b0, unsigned b1) {
    asm volatile("mma.sync.aligned.m16n8k8.row.col.f32.tf32.tf32.f32 "
                 "{%0,%1,%2,%3}, {%4,%5,%6,%7}, {%8,%9}, {%0,%1,%2,%3};"
                 : "+f"(c0), "+f"(c1), "+f"(c2), "+f"(c3)
                 : "r"(a0), "r"(a1), "r"(a2), "r"(a3), "r"(b0), "r"(b1));
}

__device__ __forceinline__ void cp16(float* smem_dst, const float* g_src) {
    unsigned s = (unsigned)__cvta_generic_to_shared(smem_dst);
    asm volatile("cp.async.cg.shared.global [%0], [%1], 16;" :: "r"(s), "l"(g_src));
}
__device__ __forceinline__ void cp_commit() {
    asm volatile("cp.async.commit_group;" ::: "memory");
}
__device__ __forceinline__ void cp_wait0() {
    asm volatile("cp.async.wait_group 0;" ::: "memory");
}

// sigmoid via MUFU (2 SFU ops, concurrent with tensor pipe)
__device__ __forceinline__ float sigmoid_mufu(float x) {
    float e;
    asm("ex2.approx.f32 %0, %1;" : "=f"(e) : "f"(x * -1.4426950408889634f));
    float r;
    asm("rcp.approx.f32 %0, %1;" : "=f"(r) : "f"(1.0f + e));
    return r;
}

// ---------------- fused weight pre-round (single launch) ----------------
__global__ __launch_bounds__(256) void cvt_all(
    const float4* __restrict__ w0, float4* __restrict__ o0,
    const float4* __restrict__ w1, float4* __restrict__ o1,
    const float4* __restrict__ w2, float4* __restrict__ o2,
    const float4* __restrict__ w3, float4* __restrict__ o3,
    const float4* __restrict__ w4, float4* __restrict__ o4)
{
    int i = blockIdx.x * 256 + threadIdx.x;
    const float4* src; float4* dst; int j;
    if      (i < 196608) { src = w0; dst = o0; j = i; }
    else if (i < 262144) { src = w1; dst = o1; j = i - 196608; }
    else if (i < 327680) { src = w2; dst = o2; j = i - 262144; }
    else if (i < 589824) { src = w3; dst = o3; j = i - 327680; }
    else                 { src = w4; dst = o4; j = i - 589824; }
    float4 v = src[j];
    v.x = cvt_tf32(v.x); v.y = cvt_tf32(v.y);
    v.z = cvt_tf32(v.z); v.w = cvt_tf32(v.w);
    dst[j] = v;
}

// ---------------- LayerNorm (output rounded to tf32) ----------------
__global__ __launch_bounds__(128) void ln_kernel(const float* __restrict__ x,
                                                 const float* __restrict__ g,
                                                 const float* __restrict__ bta,
                                                 float* __restrict__ out)
{
    int row = blockIdx.x;
    int t = threadIdx.x;
    const float4* xr = (const float4*)(x + (size_t)row * CCH);
    float4 v = xr[t];
    float s  = v.x + v.y + v.z + v.w;
    float s2 = v.x*v.x + v.y*v.y + v.z*v.z + v.w*v.w;
    #pragma unroll
    for (int o = 16; o; o >>= 1) {
        s  += __shfl_xor_sync(0xffffffffu, s,  o);
        s2 += __shfl_xor_sync(0xffffffffu, s2, o);
    }
    __shared__ float ss[4], ss2[4];
    int w = t >> 5, l = t & 31;
    if (l == 0) { ss[w] = s; ss2[w] = s2; }
    __syncthreads();
    s  = ss[0]  + ss[1]  + ss[2]  + ss[3];
    s2 = ss2[0] + ss2[1] + ss2[2] + ss2[3];
    float m   = s  * (1.0f/512.0f);
    float var = s2 * (1.0f/512.0f) - m*m;
    float r   = rsqrtf(var + 1e-5f);
    float4 gv = ((const float4*)g)[t];
    float4 bv = ((const float4*)bta)[t];
    float4 o4;
    o4.x = cvt_tf32((v.x - m) * r * gv.x + bv.x);
    o4.y = cvt_tf32((v.y - m) * r * gv.y + bv.y);
    o4.z = cvt_tf32((v.z - m) * r * gv.z + bv.z);
    o4.w = cvt_tf32((v.w - m) * r * gv.w + bv.w);
    ((float4*)(out + (size_t)row * CCH))[t] = o4;
}

// ---------------- TF32 GEMM: BM=128 BN=64 BK=32, 128 thr, 4 CTAs/SM ----------------
// TLP-based latency hiding (no fragment double-buffer -> ~105 regs).
#define G_AS_STRIDE 36
#define G_BS_STRIDE 72
#define G_AS_SZ (128*G_AS_STRIDE)
#define G_BS_SZ (32*G_BS_STRIDE)
#define G_SMEM ((2*G_AS_SZ + 2*G_BS_SZ)*4)   // 55296 B

template<bool HAS_ADD, bool HAS_ADD2, bool GELU_EPI, bool ROUND_OUT>
__global__ __launch_bounds__(128, 4) void gemm_tf32(
    const float* __restrict__ A, const float* __restrict__ W,
    const float* __restrict__ bias,
    const float* __restrict__ addm, const float* __restrict__ addm2,
    float* __restrict__ Cmat, int M, int N, int K)
{
    extern __shared__ float sh[];
    float* As = sh;
    float* Bs = sh + 2*G_AS_SZ;

    const int tid  = threadIdx.x;
    const int warp = tid >> 5, lane = tid & 31;
    const int gid  = lane >> 2, tig = lane & 3;
    const int wm   = (warp >> 1) * 64;
    const int wn   = (warp & 1) * 32;
    const int bm   = blockIdx.y * 128, bn = blockIdx.x * 64;

    const int ar = tid >> 3, ac = (tid & 7) * 4;
    const int br = tid >> 4, bc = (tid & 15) * 4;

    const float* Ag = A + (size_t)bm * K;
    const float* Wg = W + bn;

    float acc[4][4][4] = {};
    const int nk = K >> 5;

    #pragma unroll
    for (int i = 0; i < 8; i++)
        cp16(As + (ar + i*16)*G_AS_STRIDE + ac, Ag + (size_t)(ar + i*16) * K + ac);
    #pragma unroll
    for (int i = 0; i < 4; i++)
        cp16(Bs + (br + i*8)*G_BS_STRIDE + bc, Wg + (size_t)(br + i*8) * N + bc);
    cp_commit();

    for (int kt = 0; kt < nk; kt++) {
        cp_wait0();
        __syncthreads();
        if (kt + 1 < nk) {
            int k0 = (kt + 1) << 5;
            float* asn = As + ((kt + 1) & 1) * G_AS_SZ;
            float* bsn = Bs + ((kt + 1) & 1) * G_BS_SZ;
            #pragma unroll
            for (int i = 0; i < 8; i++)
                cp16(asn + (ar + i*16)*G_AS_STRIDE + ac, Ag + (size_t)(ar + i*16) * K + k0 + ac);
            #pragma unroll
            for (int i = 0; i < 4; i++)
                cp16(bsn + (br + i*8)*G_BS_STRIDE + bc, Wg + (size_t)(k0 + br + i*8) * N + bc);
            cp_commit();
        }
        const float* as = As + (kt & 1) * G_AS_SZ;
        const float* bs = Bs + (kt & 1) * G_BS_SZ;

        #pragma unroll
        for (int ks = 0; ks < 4; ks++) {
            unsigned af[4][4], bf[4][2];
            #pragma unroll
            for (int mt = 0; mt < 4; mt++) {
                const float* ap = as + (wm + mt*16 + gid)*G_AS_STRIDE + ks*8 + tig;
                af[mt][0] = __float_as_uint(ap[0]);
                af[mt][1] = __float_as_uint(ap[8*G_AS_STRIDE]);
                af[mt][2] = __float_as_uint(ap[4]);
                af[mt][3] = __float_as_uint(ap[8*G_AS_STRIDE + 4]);
            }
            #pragma unroll
            for (int nt = 0; nt < 4; nt++) {
                const float* bp = bs + (ks*8 + tig)*G_BS_STRIDE + wn + nt*8 + gid;
                bf[nt][0] = __float_as_uint(bp[0]);
                bf[nt][1] = __float_as_uint(bp[4*G_BS_STRIDE]);
            }
            #pragma unroll
            for (int mt = 0; mt < 4; mt++)
                #pragma unroll
                for (int nt = 0; nt < 4; nt++)
                    mma_tf32(acc[mt][nt][0], acc[mt][nt][1], acc[mt][nt][2], acc[mt][nt][3],
                             af[mt][0], af[mt][1], af[mt][2], af[mt][3],
                             bf[nt][0], bf[nt][1]);
        }
    }

    #pragma unroll
    for (int mt = 0; mt < 4; mt++) {
        int r0 = bm + wm + mt*16 + gid;
        #pragma unroll
        for (int nt = 0; nt < 4; nt++) {
            int c0 = bn + wn + nt*8 + 2*tig;
            float2 bv = *(const float2*)(bias + c0);
            float v0 = acc[mt][nt][0] + bv.x;
            float v1 = acc[mt][nt][1] + bv.y;
            float v2 = acc[mt][nt][2] + bv.x;
            float v3 = acc[mt][nt][3] + bv.y;
            size_t o0 = (size_t)r0 * N + c0;
            size_t o1 = (size_t)(r0 + 8) * N + c0;
            if (HAS_ADD) {
                float2 d0 = *(const float2*)(addm + o0);
                float2 d1 = *(const float2*)(addm + o1);
                v0 += d0.x; v1 += d0.y; v2 += d1.x; v3 += d1.y;
            }
            if (HAS_ADD2) {
                float2 d0 = *(const float2*)(addm2 + o0);
                float2 d1 = *(const float2*)(addm2 + o1);
                v0 += d0.x; v1 += d0.y; v2 += d1.x; v3 += d1.y;
            }
            if (GELU_EPI) {
                v0 = 0.5f * v0 * (1.0f + erff(v0 * 0.70710678118654752f));
                v1 = 0.5f * v1 * (1.0f + erff(v1 * 0.70710678118654752f));
                v2 = 0.5f * v2 * (1.0f + erff(v2 * 0.70710678118654752f));
                v3 = 0.5f * v3 * (1.0f + erff(v3 * 0.70710678118654752f));
            }
            if (ROUND_OUT) {
                v0 = cvt_tf32(v0); v1 = cvt_tf32(v1);
                v2 = cvt_tf32(v2); v3 = cvt_tf32(v3);
            }
            *(float2*)(Cmat + o0) = make_float2(v0, v1);
            *(float2*)(Cmat + o1) = make_float2(v2, v3);
        }
    }
}

// ---------------- attention: s-split x2, 2 CTAs/SM ----------------
#define A_KS_STRIDE 68
#define A_VS_STRIDE 72
#define A_SS_STRIDE 36
#define A_KS_SZ (64*A_KS_STRIDE)
#define A_VS_SZ (64*A_VS_STRIDE)
#define A_SMEM ((2*A_KS_SZ + 2*A_VS_SZ + 128*A_SS_STRIDE)*4)   // 90112 B
#define NKT (TT/64)   // 32 s-tiles total; 16 per s-half

__global__ __launch_bounds__(256, 2) void attn_tf32(const float* __restrict__ qkv,
                                                    const float* __restrict__ coul,
                                                    float* __restrict__ yatt0,
                                                    float* __restrict__ yatt1)
{
    extern __shared__ float sh[];
    float* Ks = sh;
    float* Vs = sh + 2*A_KS_SZ;
    float* Ss = Vs + 2*A_VS_SZ;

    const int bh = blockIdx.x;                 // heads fastest -> coulomb L2 sharing
    const int b = bh >> 3, h = bh & 7;
    const int ttile = blockIdx.y >> 1;
    const int shalf = blockIdx.y & 1;          // s-range half
    const int t0 = ttile * 128;
    const int kt0 = shalf * (NKT/2), kt1 = kt0 + (NKT/2);
    const int tid = threadIdx.x, warp = tid >> 5, lane = tid & 31;
    const int gid = lane >> 2, tig = lane & 3;
    const int lr = tid >> 4, lc = (tid & 15) * 4;
    const int r0 = warp*16 + gid;

    // Q fragments in registers
    float qf[8][4];
    {
        const float* q0 = qkv + (size_t)(b*TT + t0 + r0) * C3 + h*DD;
        #pragma unroll
        for (int kd = 0; kd < 8; kd++) {
            qf[kd][0] = q0[kd*8 + tig]            * 0.125f;
            qf[kd][1] = q0[8*C3 + kd*8 + tig]     * 0.125f;
            qf[kd][2] = q0[kd*8 + tig + 4]        * 0.125f;
            qf[kd][3] = q0[8*C3 + kd*8 + tig + 4] * 0.125f;
        }
    }

    float yacc[8][4];
    #pragma unroll
    for (int i = 0; i < 8; i++) { yacc[i][0]=0.f; yacc[i][1]=0.f; yacc[i][2]=0.f; yacc[i][3]=0.f; }

    const float* cb0 = coul + (size_t)b * TT * TT + (size_t)(t0 + r0) * TT;
    const float* cb1 = cb0 + 8 * TT;
    const float* kbase = qkv + (size_t)(b*TT) * C3 + CCH + h*DD;

    // prologue: cp.async first s-tile of this half
    {
        const float* k0p = kbase + (size_t)(kt0 * 64) * C3;
        #pragma unroll
        for (int i = 0; i < 4; i++) {
            cp16(Ks + ((kt0&1)*A_KS_SZ) + (lr + i*16)*A_KS_STRIDE + lc, k0p + (size_t)(lr + i*16) * C3 + lc);
            cp16(Vs + ((kt0&1)*A_VS_SZ) + (lr + i*16)*A_VS_STRIDE + lc, k0p + CCH + (size_t)(lr + i*16) * C3 + lc);
        }
        cp_commit();
    }

    for (int kt = kt0; kt < kt1; kt++) {
        cp_wait0();
        __syncthreads();
        if (kt + 1 < kt1) {
            const float* kn = kbase + (size_t)((kt + 1) * 64) * C3;
            float* kd_ = Ks + ((kt + 1) & 1) * A_KS_SZ;
            float* vd_ = Vs + ((kt + 1) & 1) * A_VS_SZ;
            #pragma unroll
            for (int i = 0; i < 4; i++) {
                cp16(kd_ + (lr + i*16)*A_KS_STRIDE + lc, kn + (size_t)(lr + i*16) * C3 + lc);
                cp16(vd_ + (lr + i*16)*A_VS_STRIDE + lc, kn + CCH + (size_t)(lr + i*16) * C3 + lc);
            }
            cp_commit();
        }
        const float* ksb = Ks + (kt & 1) * A_KS_SZ;
        const float* vsb = Vs + (kt & 1) * A_VS_SZ;
        const int s0 = kt * 64;

        #pragma unroll
        for (int hf = 0; hf < 2; hf++) {
            float2 c0[4], c1[4];
            #pragma unroll
            for (int nt = 0; nt < 4; nt++) {
                int sc = s0 + hf*32 + nt*8 + 2*tig;
                c0[nt] = *(const float2*)(cb0 + sc);
                c1[nt] = *(const float2*)(cb1 + sc);
            }

            float sacc[4][4];
            #pragma unroll
            for (int i = 0; i < 4; i++) { sacc[i][0]=0.f; sacc[i][1]=0.f; sacc[i][2]=0.f; sacc[i][3]=0.f; }
            #pragma unroll
            for (int kd = 0; kd < 8; kd++) {
                unsigned a0 = __float_as_uint(qf[kd][0]);
                unsigned a1 = __float_as_uint(qf[kd][1]);
                unsigned a2 = __float_as_uint(qf[kd][2]);
                unsigned a3 = __float_as_uint(qf[kd][3]);
                #pragma unroll
                for (int nt = 0; nt < 4; nt++) {
                    const float* bp = ksb + (hf*32 + nt*8 + gid)*A_KS_STRIDE + kd*8 + tig;
                    mma_tf32(sacc[nt][0], sacc[nt][1], sacc[nt][2], sacc[nt][3],
                             a0, a1, a2, a3,
                             __float_as_uint(bp[0]), __float_as_uint(bp[4]));
                }
            }

            #pragma unroll
            for (int nt = 0; nt < 4; nt++) {
                float* sp = Ss + r0*A_SS_STRIDE + nt*8 + 2*tig;
                sp[0]                 = cvt_tf32(sigmoid_mufu(sacc[nt][0]) * c0[nt].x);
                sp[1]                 = cvt_tf32(sigmoid_mufu(sacc[nt][1]) * c0[nt].y);
                sp[8*A_SS_STRIDE]     = cvt_tf32(sigmoid_mufu(sacc[nt][2]) * c1[nt].x);
                sp[8*A_SS_STRIDE + 1] = cvt_tf32(sigmoid_mufu(sacc[nt][3]) * c1[nt].y);
            }
            __syncwarp();

            #pragma unroll
            for (int ks = 0; ks < 4; ks++) {
                const float* ap = Ss + r0*A_SS_STRIDE + ks*8 + tig;
                unsigned a0 = __float_as_uint(ap[0]);
                unsigned a1 = __float_as_uint(ap[8*A_SS_STRIDE]);
                unsigned a2 = __float_as_uint(ap[4]);
                unsigned a3 = __float_as_uint(ap[8*A_SS_STRIDE + 4]);
                #pragma unroll
                for (int nt = 0; nt < 8; nt++) {
                    const float* bp = vsb + (hf*32 + ks*8 + tig)*A_VS_STRIDE + nt*8 + gid;
                    mma_tf32(yacc[nt][0], yacc[nt][1], yacc[nt][2], yacc[nt][3],
                             a0, a1, a2, a3,
                             __float_as_uint(bp[0]), __float_as_uint(bp[4*A_VS_STRIDE]));
                }
            }
            __syncwarp();
        }
    }

    // store partial Y to this s-half's buffer
    float* ybuf = shalf ? yatt1 : yatt0;
    float* ob = ybuf + (size_t)(b*TT + t0 + r0) * CCH + h*DD;
    #pragma unroll
    for (int nt = 0; nt < 8; nt++) {
        int c = nt*8 + 2*tig;
        *(float2*)(ob + c)           = make_float2(yacc[nt][0], yacc[nt][1]);
        *(float2*)(ob + 8*CCH + c)   = make_float2(yacc[nt][2], yacc[nt][3]);
    }
}

// ---------------- launch ----------------
extern "C" void kernel_launch(void* const* d_in, const int* in_sizes, int n_in,
                              void* d_out, int out_size)
{
    const float* x      = (const float*)d_in[0];
    const float* coul   = (const float*)d_in[2];
    const float* ln1g   = (const float*)d_in[3];
    const float* ln1b   = (const float*)d_in[4];
    const float* w_attn = (const float*)d_in[5];
    const float* b_attn = (const float*)d_in[6];
    const float* w_self = (const float*)d_in[7];
    const float* b_self = (const float*)d_in[8];
    const float* w_proj = (const float*)d_in[9];
    const float* b_proj = (const float*)d_in[10];
    const float* ln2g   = (const float*)d_in[11];
    const float* ln2b   = (const float*)d_in[12];
    const float* w_fc   = (const float*)d_in[13];
    const float* b_fc   = (const float*)d_in[14];
    const float* w_fcp  = (const float*)d_in[15];
    const float* b_fcp  = (const float*)d_in[16];
    float* out = (float*)d_out;

    float *h, *qkvp, *att0, *att1, *yp, *y2p, *h2p, *fcp;
    float *wattn, *wself, *wproj, *wfc, *wfcp;
    cudaGetSymbolAddress((void**)&h,    g_h);
    cudaGetSymbolAddress((void**)&qkvp, g_qkv);
    cudaGetSymbolAddress((void**)&att0, g_att0);
    cudaGetSymbolAddress((void**)&att1, g_att1);
    cudaGetSymbolAddress((void**)&yp,   g_y);
    cudaGetSymbolAddress((void**)&y2p,  g_y2);
    cudaGetSymbolAddress((void**)&h2p,  g_h2);
    cudaGetSymbolAddress((void**)&fcp,  g_fc);
    cudaGetSymbolAddress((void**)&wattn, g_wattn);
    cudaGetSymbolAddress((void**)&wself, g_wself);
    cudaGetSymbolAddress((void**)&wproj, g_wproj);
    cudaGetSymbolAddress((void**)&wfc,   g_wfc);
    cudaGetSymbolAddress((void**)&wfcp,  g_wfcp);

    cudaFuncSetAttribute((const void*)gemm_tf32<false,false,false,true>,  cudaFuncAttributeMaxDynamicSharedMemorySize, G_SMEM);
    cudaFuncSetAttribute((const void*)gemm_tf32<false,false,true,true>,   cudaFuncAttributeMaxDynamicSharedMemorySize, G_SMEM);
    cudaFuncSetAttribute((const void*)gemm_tf32<true,true,false,true>,    cudaFuncAttributeMaxDynamicSharedMemorySize, G_SMEM);
    cudaFuncSetAttribute((const void*)gemm_tf32<false,false,false,false>, cudaFuncAttributeMaxDynamicSharedMemorySize, G_SMEM);
    cudaFuncSetAttribute(attn_tf32, cudaFuncAttributeMaxDynamicSharedMemorySize, A_SMEM);

    // 0) pre-round weights to tf32
    cvt_all<<<3328, 256>>>((const float4*)w_attn, (float4*)wattn,
                           (const float4*)w_self, (float4*)wself,
                           (const float4*)w_proj, (float4*)wproj,
                           (const float4*)w_fc,   (float4*)wfc,
                           (const float4*)w_fcp,  (float4*)wfcp);

    // 1) h = LN1(x)
    ln_kernel<<<NROWS, 128>>>(x, ln1g, ln1b, h);
    // 2) qkv = h @ w_attn + b_attn
    gemm_tf32<false,false,false,true><<<dim3(24,32), 128, G_SMEM>>>(h, wattn, b_attn, nullptr, nullptr, qkvp, NROWS, C3, CCH);
    // 3) attention, s-split x2 -> two partial buffers
    attn_tf32<<<dim3(BB*HH, (TT/128)*2), 256, A_SMEM>>>(qkvp, coul, att0, att1);
    // 4) y = att0 + att1 + h @ w_self + b_self
    gemm_tf32<true,true,false,true><<<dim3(8,32), 128, G_SMEM>>>(h, wself, b_self, att0, att1, yp, NROWS, CCH, CCH);
    // 5) y2 = y @ w_proj + b_proj
    gemm_tf32<false,false,false,false><<<dim3(8,32), 128, G_SMEM>>>(yp, wproj, b_proj, nullptr, nullptr, y2p, NROWS, CCH, CCH);
    // 6) h2 = LN2(y2)
    ln_kernel<<<NROWS, 128>>>(y2p, ln2g, ln2b, h2p);
    // 7) fc = gelu(h2 @ w_fc + b_fc)
    gemm_tf32<false,false,true,true><<<dim3(32,32), 128, G_SMEM>>>(h2p, wfc, b_fc, nullptr, nullptr, fcp, NROWS, 4*CCH, CCH);
    // 8) out = fc @ w_fc_proj + b_fc_proj
    gemm_tf32<false,false,false,false><<<dim3(8,32), 128, G_SMEM>>>(fcp, wfcp, b_fcp, nullptr, nullptr, out, NROWS, CCH, 4*CCH);
}

// round 10
// speedup vs baseline: 1.2578x; 1.0317x over previous
#include <cuda_runtime.h>
#include <math.h>

// Problem constants
#define BB 2
#define TT 2048
#define CCH 512
#define HH 8
#define DD 64
#define NROWS (BB*TT)   // 4096
#define C3 (3*CCH)      // 1536

// ---------------- scratch ----------------
__device__ float g_h   [NROWS*CCH];
__device__ float g_qkv [NROWS*C3];
__device__ float g_att0[NROWS*CCH];
__device__ float g_att1[NROWS*CCH];
__device__ float g_y   [NROWS*CCH];
__device__ float g_y2  [NROWS*CCH];
__device__ float g_h2  [NROWS*CCH];
__device__ float g_fc  [NROWS*4*CCH];
// pre-rounded (tf32) weights
__device__ float g_wattn[CCH*C3];
__device__ float g_wself[CCH*CCH];
__device__ float g_wproj[CCH*CCH];
__device__ float g_wfc  [CCH*4*CCH];
__device__ float g_wfcp [4*CCH*CCH];

// ---------------- helpers ----------------
__device__ __forceinline__ float cvt_tf32(float x) {
    unsigned u; asm("cvt.rna.tf32.f32 %0, %1;" : "=r"(u) : "f"(x));
    return __uint_as_float(u);
}

__device__ __forceinline__ void mma_tf32(float& c0, float& c1, float& c2, float& c3,
                                         unsigned a0, unsigned a1, unsigned a2, unsigned a3,
                                         unsigned b0, unsigned b1) {
    asm volatile("mma.sync.aligned.m16n8k8.row.col.f32.tf32.tf32.f32 "
                 "{%0,%1,%2,%3}, {%4,%5,%6,%7}, {%8,%9}, {%0,%1,%2,%3};"
                 : "+f"(c0), "+f"(c1), "+f"(c2), "+f"(c3)
                 : "r"(a0), "r"(a1), "r"(a2), "r"(a3), "r"(b0), "r"(b1));
}

// ldmatrix x4: four 8x8-b16 (= 8x4 tf32) tiles; matrix i rows from lanes 8i..8i+7.
__device__ __forceinline__ void ldsm4(unsigned& r0, unsigned& r1, unsigned& r2, unsigned& r3,
                                      unsigned addr) {
    asm volatile("ldmatrix.sync.aligned.m8n8.x4.shared.b16 {%0,%1,%2,%3}, [%4];"
                 : "=r"(r0), "=r"(r1), "=r"(r2), "=r"(r3) : "r"(addr));
}

__device__ __forceinline__ unsigned smem_u32(const void* p) {
    return (unsigned)__cvta_generic_to_shared(p);
}

__device__ __forceinline__ void cp16(float* smem_dst, const float* g_src) {
    unsigned s = (unsigned)__cvta_generic_to_shared(smem_dst);
    asm volatile("cp.async.cg.shared.global [%0], [%1], 16;" :: "r"(s), "l"(g_src));
}
__device__ __forceinline__ void cp_commit() {
    asm volatile("cp.async.commit_group;" ::: "memory");
}
__device__ __forceinline__ void cp_wait0() {
    asm volatile("cp.async.wait_group 0;" ::: "memory");
}

// sigmoid via MUFU
__device__ __forceinline__ float sigmoid_mufu(float x) {
    float e;
    asm("ex2.approx.f32 %0, %1;" : "=f"(e) : "f"(x * -1.4426950408889634f));
    float r;
    asm("rcp.approx.f32 %0, %1;" : "=f"(r) : "f"(1.0f + e));
    return r;
}

// ---------------- fused weight pre-round ----------------
__global__ __launch_bounds__(256) void cvt_all(
    const float4* __restrict__ w0, float4* __restrict__ o0,
    const float4* __restrict__ w1, float4* __restrict__ o1,
    const float4* __restrict__ w2, float4* __restrict__ o2,
    const float4* __restrict__ w3, float4* __restrict__ o3,
    const float4* __restrict__ w4, float4* __restrict__ o4)
{
    int i = blockIdx.x * 256 + threadIdx.x;
    const float4* src; float4* dst; int j;
    if      (i < 196608) { src = w0; dst = o0; j = i; }
    else if (i < 262144) { src = w1; dst = o1; j = i - 196608; }
    else if (i < 327680) { src = w2; dst = o2; j = i - 262144; }
    else if (i < 589824) { src = w3; dst = o3; j = i - 327680; }
    else                 { src = w4; dst = o4; j = i - 589824; }
    float4 v = src[j];
    v.x = cvt_tf32(v.x); v.y = cvt_tf32(v.y);
    v.z = cvt_tf32(v.z); v.w = cvt_tf32(v.w);
    dst[j] = v;
}

// ---------------- LayerNorm ----------------
__global__ __launch_bounds__(128) void ln_kernel(const float* __restrict__ x,
                                                 const float* __restrict__ g,
                                                 const float* __restrict__ bta,
                                                 float* __restrict__ out)
{
    int row = blockIdx.x;
    int t = threadIdx.x;
    const float4* xr = (const float4*)(x + (size_t)row * CCH);
    float4 v = xr[t];
    float s  = v.x + v.y + v.z + v.w;
    float s2 = v.x*v.x + v.y*v.y + v.z*v.z + v.w*v.w;
    #pragma unroll
    for (int o = 16; o; o >>= 1) {
        s  += __shfl_xor_sync(0xffffffffu, s,  o);
        s2 += __shfl_xor_sync(0xffffffffu, s2, o);
    }
    __shared__ float ss[4], ss2[4];
    int w = t >> 5, l = t & 31;
    if (l == 0) { ss[w] = s; ss2[w] = s2; }
    __syncthreads();
    s  = ss[0]  + ss[1]  + ss[2]  + ss[3];
    s2 = ss2[0] + ss2[1] + ss2[2] + ss2[3];
    float m   = s  * (1.0f/512.0f);
    float var = s2 * (1.0f/512.0f) - m*m;
    float r   = rsqrtf(var + 1e-5f);
    float4 gv = ((const float4*)g)[t];
    float4 bv = ((const float4*)bta)[t];
    float4 o4;
    o4.x = cvt_tf32((v.x - m) * r * gv.x + bv.x);
    o4.y = cvt_tf32((v.y - m) * r * gv.y + bv.y);
    o4.z = cvt_tf32((v.z - m) * r * gv.z + bv.z);
    o4.w = cvt_tf32((v.w - m) * r * gv.w + bv.w);
    ((float4*)(out + (size_t)row * CCH))[t] = o4;
}

// ---------------- TF32 GEMM: BM=128 BN=64 BK=32, 128 thr, 4 CTAs/SM ----------------
// A-fragments via ldmatrix.x4 (4 regs / 1 instr); B scalar.
#define G_AS_STRIDE 36
#define G_BS_STRIDE 72
#define G_AS_SZ (128*G_AS_STRIDE)
#define G_BS_SZ (32*G_BS_STRIDE)
#define G_SMEM ((2*G_AS_SZ + 2*G_BS_SZ)*4)   // 55296 B

template<bool HAS_ADD, bool HAS_ADD2, bool GELU_EPI, bool ROUND_OUT>
__global__ __launch_bounds__(128, 4) void gemm_tf32(
    const float* __restrict__ A, const float* __restrict__ W,
    const float* __restrict__ bias,
    const float* __restrict__ addm, const float* __restrict__ addm2,
    float* __restrict__ Cmat, int M, int N, int K)
{
    extern __shared__ float sh[];
    float* As = sh;
    float* Bs = sh + 2*G_AS_SZ;

    const int tid  = threadIdx.x;
    const int warp = tid >> 5, lane = tid & 31;
    const int gid  = lane >> 2, tig = lane & 3;
    const int lg   = lane >> 3, lw = lane & 7;    // ldmatrix lane decomposition
    const int wm   = (warp >> 1) * 64;
    const int wn   = (warp & 1) * 32;
    const int bm   = blockIdx.y * 128, bn = blockIdx.x * 64;

    const int ar = tid >> 3, ac = (tid & 7) * 4;
    const int br = tid >> 4, bc = (tid & 15) * 4;

    const float* Ag = A + (size_t)bm * K;
    const float* Wg = W + bn;

    // A-type ldmatrix per-lane offset (floats): rows (lg&1)*8 + lw, koff (lg>>1)*4
    const unsigned as_u = smem_u32(As);
    const unsigned gA_off = ((wm + (lg & 1)*8 + lw) * G_AS_STRIDE + (lg >> 1)*4) * 4u;

    float acc[4][4][4] = {};
    const int nk = K >> 5;

    #pragma unroll
    for (int i = 0; i < 8; i++)
        cp16(As + (ar + i*16)*G_AS_STRIDE + ac, Ag + (size_t)(ar + i*16) * K + ac);
    #pragma unroll
    for (int i = 0; i < 4; i++)
        cp16(Bs + (br + i*8)*G_BS_STRIDE + bc, Wg + (size_t)(br + i*8) * N + bc);
    cp_commit();

    for (int kt = 0; kt < nk; kt++) {
        cp_wait0();
        __syncthreads();
        if (kt + 1 < nk) {
            int k0 = (kt + 1) << 5;
            float* asn = As + ((kt + 1) & 1) * G_AS_SZ;
            float* bsn = Bs + ((kt + 1) & 1) * G_BS_SZ;
            #pragma unroll
            for (int i = 0; i < 8; i++)
                cp16(asn + (ar + i*16)*G_AS_STRIDE + ac, Ag + (size_t)(ar + i*16) * K + k0 + ac);
            #pragma unroll
            for (int i = 0; i < 4; i++)
                cp16(bsn + (br + i*8)*G_BS_STRIDE + bc, Wg + (size_t)(k0 + br + i*8) * N + bc);
            cp_commit();
        }
        const unsigned as_b = as_u + (unsigned)((kt & 1) * G_AS_SZ * 4) + gA_off;
        const float* bs = Bs + (kt & 1) * G_BS_SZ;

        #pragma unroll
        for (int ks = 0; ks < 4; ks++) {
            unsigned af[4][4], bf[4][2];
            #pragma unroll
            for (int mt = 0; mt < 4; mt++)
                ldsm4(af[mt][0], af[mt][1], af[mt][2], af[mt][3],
                      as_b + (unsigned)((mt*16*G_AS_STRIDE + ks*8) * 4));
            #pragma unroll
            for (int nt = 0; nt < 4; nt++) {
                const float* bp = bs + (ks*8 + tig)*G_BS_STRIDE + wn + nt*8 + gid;
                bf[nt][0] = __float_as_uint(bp[0]);
                bf[nt][1] = __float_as_uint(bp[4*G_BS_STRIDE]);
            }
            #pragma unroll
            for (int mt = 0; mt < 4; mt++)
                #pragma unroll
                for (int nt = 0; nt < 4; nt++)
                    mma_tf32(acc[mt][nt][0], acc[mt][nt][1], acc[mt][nt][2], acc[mt][nt][3],
                             af[mt][0], af[mt][1], af[mt][2], af[mt][3],
                             bf[nt][0], bf[nt][1]);
        }
    }

    #pragma unroll
    for (int mt = 0; mt < 4; mt++) {
        int r0 = bm + wm + mt*16 + gid;
        #pragma unroll
        for (int nt = 0; nt < 4; nt++) {
            int c0 = bn + wn + nt*8 + 2*tig;
            float2 bv = *(const float2*)(bias + c0);
            float v0 = acc[mt][nt][0] + bv.x;
            float v1 = acc[mt][nt][1] + bv.y;
            float v2 = acc[mt][nt][2] + bv.x;
            float v3 = acc[mt][nt][3] + bv.y;
            size_t o0 = (size_t)r0 * N + c0;
            size_t o1 = (size_t)(r0 + 8) * N + c0;
            if (HAS_ADD) {
                float2 d0 = *(const float2*)(addm + o0);
                float2 d1 = *(const float2*)(addm + o1);
                v0 += d0.x; v1 += d0.y; v2 += d1.x; v3 += d1.y;
            }
            if (HAS_ADD2) {
                float2 d0 = *(const float2*)(addm2 + o0);
                float2 d1 = *(const float2*)(addm2 + o1);
                v0 += d0.x; v1 += d0.y; v2 += d1.x; v3 += d1.y;
            }
            if (GELU_EPI) {
                v0 = 0.5f * v0 * (1.0f + erff(v0 * 0.70710678118654752f));
                v1 = 0.5f * v1 * (1.0f + erff(v1 * 0.70710678118654752f));
                v2 = 0.5f * v2 * (1.0f + erff(v2 * 0.70710678118654752f));
                v3 = 0.5f * v3 * (1.0f + erff(v3 * 0.70710678118654752f));
            }
            if (ROUND_OUT) {
                v0 = cvt_tf32(v0); v1 = cvt_tf32(v1);
                v2 = cvt_tf32(v2); v3 = cvt_tf32(v3);
            }
            *(float2*)(Cmat + o0) = make_float2(v0, v1);
            *(float2*)(Cmat + o1) = make_float2(v2, v3);
        }
    }
}

// ---------------- attention: s-split x2, ldmatrix fragments ----------------
#define A_KS_STRIDE 68
#define A_VS_STRIDE 72
#define A_SS_STRIDE 36
#define A_KS_SZ (64*A_KS_STRIDE)
#define A_VS_SZ (64*A_VS_STRIDE)
#define A_SMEM ((2*A_KS_SZ + 2*A_VS_SZ + 128*A_SS_STRIDE)*4)   // 90112 B
#define NKT (TT/64)

__global__ __launch_bounds__(256, 2) void attn_tf32(const float* __restrict__ qkv,
                                                    const float* __restrict__ coul,
                                                    float* __restrict__ yatt0,
                                                    float* __restrict__ yatt1)
{
    extern __shared__ float sh[];
    float* Ks = sh;
    float* Vs = sh + 2*A_KS_SZ;
    float* Ss = Vs + 2*A_VS_SZ;

    const int bh = blockIdx.x;
    const int b = bh >> 3, h = bh & 7;
    const int ttile = blockIdx.y >> 1;
    const int shalf = blockIdx.y & 1;
    const int t0 = ttile * 128;
    const int kt0 = shalf * (NKT/2), kt1 = kt0 + (NKT/2);
    const int tid = threadIdx.x, warp = tid >> 5, lane = tid & 31;
    const int gid = lane >> 2, tig = lane & 3;
    const int lg = lane >> 3, lw = lane & 7;
    const int lr = tid >> 4, lc = (tid & 15) * 4;
    const int r0 = warp*16 + gid;

    // ldmatrix per-lane offsets (bytes)
    const unsigned ks_u = smem_u32(Ks);
    const unsigned ss_u = smem_u32(Ss);
    // B-type (QK from Ks): row (lg>>1)*8 + lw within 16-row pair block, koff (lg&1)*4
    const unsigned qkB_off = (((lg >> 1)*8 + lw) * A_KS_STRIDE + (lg & 1)*4) * 4u;
    // A-type (PV from Ss): row warp*16 + (lg&1)*8 + lw, koff (lg>>1)*4
    const unsigned pvA_off = ((warp*16 + (lg & 1)*8 + lw) * A_SS_STRIDE + (lg >> 1)*4) * 4u;

    // Q fragments in registers
    float qf[8][4];
    {
        const float* q0 = qkv + (size_t)(b*TT + t0 + r0) * C3 + h*DD;
        #pragma unroll
        for (int kd = 0; kd < 8; kd++) {
            qf[kd][0] = q0[kd*8 + tig]            * 0.125f;
            qf[kd][1] = q0[8*C3 + kd*8 + tig]     * 0.125f;
            qf[kd][2] = q0[kd*8 + tig + 4]        * 0.125f;
            qf[kd][3] = q0[8*C3 + kd*8 + tig + 4] * 0.125f;
        }
    }

    float yacc[8][4];
    #pragma unroll
    for (int i = 0; i < 8; i++) { yacc[i][0]=0.f; yacc[i][1]=0.f; yacc[i][2]=0.f; yacc[i][3]=0.f; }

    const float* cb0 = coul + (size_t)b * TT * TT + (size_t)(t0 + r0) * TT;
    const float* cb1 = cb0 + 8 * TT;
    const float* kbase = qkv + (size_t)(b*TT) * C3 + CCH + h*DD;

    {
        const float* k0p = kbase + (size_t)(kt0 * 64) * C3;
        #pragma unroll
        for (int i = 0; i < 4; i++) {
            cp16(Ks + ((kt0&1)*A_KS_SZ) + (lr + i*16)*A_KS_STRIDE + lc, k0p + (size_t)(lr + i*16) * C3 + lc);
            cp16(Vs + ((kt0&1)*A_VS_SZ) + (lr + i*16)*A_VS_STRIDE + lc, k0p + CCH + (size_t)(lr + i*16) * C3 + lc);
        }
        cp_commit();
    }

    for (int kt = kt0; kt < kt1; kt++) {
        cp_wait0();
        __syncthreads();
        if (kt + 1 < kt1) {
            const float* kn = kbase + (size_t)((kt + 1) * 64) * C3;
            float* kd_ = Ks + ((kt + 1) & 1) * A_KS_SZ;
            float* vd_ = Vs + ((kt + 1) & 1) * A_VS_SZ;
            #pragma unroll
            for (int i = 0; i < 4; i++) {
                cp16(kd_ + (lr + i*16)*A_KS_STRIDE + lc, kn + (size_t)(lr + i*16) * C3 + lc);
                cp16(vd_ + (lr + i*16)*A_VS_STRIDE + lc, kn + CCH + (size_t)(lr + i*16) * C3 + lc);
            }
            cp_commit();
        }
        const unsigned ksb_u = ks_u + (unsigned)((kt & 1) * A_KS_SZ * 4) + qkB_off;
        const float* vsb = Vs + (kt & 1) * A_VS_SZ;
        const int s0 = kt * 64;

        #pragma unroll
        for (int hf = 0; hf < 2; hf++) {
            float2 c0[4], c1[4];
            #pragma unroll
            for (int nt = 0; nt < 4; nt++) {
                int sc = s0 + hf*32 + nt*8 + 2*tig;
                c0[nt] = *(const float2*)(cb0 + sc);
                c1[nt] = *(const float2*)(cb1 + sc);
            }

            // S = Q @ K^T : B-frags via ldmatrix (one x4 covers 2 nt)
            float sacc[4][4];
            #pragma unroll
            for (int i = 0; i < 4; i++) { sacc[i][0]=0.f; sacc[i][1]=0.f; sacc[i][2]=0.f; sacc[i][3]=0.f; }
            #pragma unroll
            for (int kd = 0; kd < 8; kd++) {
                unsigned a0 = __float_as_uint(qf[kd][0]);
                unsigned a1 = __float_as_uint(qf[kd][1]);
                unsigned a2 = __float_as_uint(qf[kd][2]);
                unsigned a3 = __float_as_uint(qf[kd][3]);
                #pragma unroll
                for (int p = 0; p < 2; p++) {
                    unsigned b0e, b1e, b0o, b1o;
                    ldsm4(b0e, b1e, b0o, b1o,
                          ksb_u + (unsigned)(((hf*32 + p*16)*A_KS_STRIDE + kd*8) * 4));
                    mma_tf32(sacc[2*p][0], sacc[2*p][1], sacc[2*p][2], sacc[2*p][3],
                             a0, a1, a2, a3, b0e, b1e);
                    mma_tf32(sacc[2*p+1][0], sacc[2*p+1][1], sacc[2*p+1][2], sacc[2*p+1][3],
                             a0, a1, a2, a3, b0o, b1o);
                }
            }

            // sigmoid(MUFU) * coulomb -> Ss (STS.64, warp-private rows)
            #pragma unroll
            for (int nt = 0; nt < 4; nt++) {
                float* sp = Ss + r0*A_SS_STRIDE + nt*8 + 2*tig;
                *(float2*)(sp) = make_float2(
                    cvt_tf32(sigmoid_mufu(sacc[nt][0]) * c0[nt].x),
                    cvt_tf32(sigmoid_mufu(sacc[nt][1]) * c0[nt].y));
                *(float2*)(sp + 8*A_SS_STRIDE) = make_float2(
                    cvt_tf32(sigmoid_mufu(sacc[nt][2]) * c1[nt].x),
                    cvt_tf32(sigmoid_mufu(sacc[nt][3]) * c1[nt].y));
            }
            __syncwarp();

            // Y += S_half @ V_half : A-frags via ldmatrix.x4
            #pragma unroll
            for (int ks = 0; ks < 4; ks++) {
                unsigned a0, a1, a2, a3;
                ldsm4(a0, a1, a2, a3, ss_u + pvA_off + (unsigned)(ks*8*4));
                #pragma unroll
                for (int nt = 0; nt < 8; nt++) {
                    const float* bp = vsb + (hf*32 + ks*8 + tig)*A_VS_STRIDE + nt*8 + gid;
                    mma_tf32(yacc[nt][0], yacc[nt][1], yacc[nt][2], yacc[nt][3],
                             a0, a1, a2, a3,
                             __float_as_uint(bp[0]), __float_as_uint(bp[4*A_VS_STRIDE]));
                }
            }
            __syncwarp();
        }
    }

    float* ybuf = shalf ? yatt1 : yatt0;
    float* ob = ybuf + (size_t)(b*TT + t0 + r0) * CCH + h*DD;
    #pragma unroll
    for (int nt = 0; nt < 8; nt++) {
        int c = nt*8 + 2*tig;
        *(float2*)(ob + c)           = make_float2(yacc[nt][0], yacc[nt][1]);
        *(float2*)(ob + 8*CCH + c)   = make_float2(yacc[nt][2], yacc[nt][3]);
    }
}

// ---------------- launch ----------------
extern "C" void kernel_launch(void* const* d_in, const int* in_sizes, int n_in,
                              void* d_out, int out_size)
{
    const float* x      = (const float*)d_in[0];
    const float* coul   = (const float*)d_in[2];
    const float* ln1g   = (const float*)d_in[3];
    const float* ln1b   = (const float*)d_in[4];
    const float* w_attn = (const float*)d_in[5];
    const float* b_attn = (const float*)d_in[6];
    const float* w_self = (const float*)d_in[7];
    const float* b_self = (const float*)d_in[8];
    const float* w_proj = (const float*)d_in[9];
    const float* b_proj = (const float*)d_in[10];
    const float* ln2g   = (const float*)d_in[11];
    const float* ln2b   = (const float*)d_in[12];
    const float* w_fc   = (const float*)d_in[13];
    const float* b_fc   = (const float*)d_in[14];
    const float* w_fcp  = (const float*)d_in[15];
    const float* b_fcp  = (const float*)d_in[16];
    float* out = (float*)d_out;

    float *h, *qkvp, *att0, *att1, *yp, *y2p, *h2p, *fcp;
    float *wattn, *wself, *wproj, *wfc, *wfcp;
    cudaGetSymbolAddress((void**)&h,    g_h);
    cudaGetSymbolAddress((void**)&qkvp, g_qkv);
    cudaGetSymbolAddress((void**)&att0, g_att0);
    cudaGetSymbolAddress((void**)&att1, g_att1);
    cudaGetSymbolAddress((void**)&yp,   g_y);
    cudaGetSymbolAddress((void**)&y2p,  g_y2);
    cudaGetSymbolAddress((void**)&h2p,  g_h2);
    cudaGetSymbolAddress((void**)&fcp,  g_fc);
    cudaGetSymbolAddress((void**)&wattn, g_wattn);
    cudaGetSymbolAddress((void**)&wself, g_wself);
    cudaGetSymbolAddress((void**)&wproj, g_wproj);
    cudaGetSymbolAddress((void**)&wfc,   g_wfc);
    cudaGetSymbolAddress((void**)&wfcp,  g_wfcp);

    cudaFuncSetAttribute((const void*)gemm_tf32<false,false,false,true>,  cudaFuncAttributeMaxDynamicSharedMemorySize, G_SMEM);
    cudaFuncSetAttribute((const void*)gemm_tf32<false,false,true,true>,   cudaFuncAttributeMaxDynamicSharedMemorySize, G_SMEM);
    cudaFuncSetAttribute((const void*)gemm_tf32<true,true,false,true>,    cudaFuncAttributeMaxDynamicSharedMemorySize, G_SMEM);
    cudaFuncSetAttribute((const void*)gemm_tf32<false,false,false,false>, cudaFuncAttributeMaxDynamicSharedMemorySize, G_SMEM);
    cudaFuncSetAttribute(attn_tf32, cudaFuncAttributeMaxDynamicSharedMemorySize, A_SMEM);

    // 0) pre-round weights to tf32
    cvt_all<<<3328, 256>>>((const float4*)w_attn, (float4*)wattn,
                           (const float4*)w_self, (float4*)wself,
                           (const float4*)w_proj, (float4*)wproj,
                           (const float4*)w_fc,   (float4*)wfc,
                           (const float4*)w_fcp,  (float4*)wfcp);

    // 1) h = LN1(x)
    ln_kernel<<<NROWS, 128>>>(x, ln1g, ln1b, h);
    // 2) qkv = h @ w_attn + b_attn
    gemm_tf32<false,false,false,true><<<dim3(24,32), 128, G_SMEM>>>(h, wattn, b_attn, nullptr, nullptr, qkvp, NROWS, C3, CCH);
    // 3) attention, s-split x2
    attn_tf32<<<dim3(BB*HH, (TT/128)*2), 256, A_SMEM>>>(qkvp, coul, att0, att1);
    // 4) y = att0 + att1 + h @ w_self + b_self
    gemm_tf32<true,true,false,true><<<dim3(8,32), 128, G_SMEM>>>(h, wself, b_self, att0, att1, yp, NROWS, CCH, CCH);
    // 5) y2 = y @ w_proj + b_proj
    gemm_tf32<false,false,false,false><<<dim3(8,32), 128, G_SMEM>>>(yp, wproj, b_proj, nullptr, nullptr, y2p, NROWS, CCH, CCH);
    // 6) h2 = LN2(y2)
    ln_kernel<<<NROWS, 128>>>(y2p, ln2g, ln2b, h2p);
    // 7) fc = gelu(h2 @ w_fc + b_fc)
    gemm_tf32<false,false,true,true><<<dim3(32,32), 128, G_SMEM>>>(h2p, wfc, b_fc, nullptr, nullptr, fcp, NROWS, 4*CCH, CCH);
    // 8) out = fc @ w_fc_proj + b_fc_proj
    gemm_tf32<false,false,false,false><<<dim3(8,32), 128, G_SMEM>>>(fcp, wfcp, b_fcp, nullptr, nullptr, out, NROWS, CCH, 4*CCH);
}

// round 14
// speedup vs baseline: 1.3136x; 1.0443x over previous
#include <cuda_runtime.h>
#include <stdint.h>
#include <math.h>

// Problem constants
#define BB 2
#define TT 2048
#define CCH 512
#define HH 8
#define DD 64
#define NROWS (BB*TT)   // 4096
#define C3 (3*CCH)      // 1536

// ---------------- scratch ----------------
__device__ float g_h   [NROWS*CCH];
__device__ float g_qkv [NROWS*C3];
__device__ float g_att0[NROWS*CCH];
__device__ float g_att1[NROWS*CCH];
__device__ float g_y   [NROWS*CCH];
__device__ float g_y2  [NROWS*CCH];
__device__ float g_h2  [NROWS*CCH];
__device__ float g_fc  [NROWS*4*CCH];
// pre-rounded (tf32) weights
__device__ float g_wattn[CCH*C3];
__device__ float g_wself[CCH*CCH];
__device__ float g_wproj[CCH*CCH];
__device__ float g_wfc  [CCH*4*CCH];
__device__ float g_wfcp [4*CCH*CCH];

// ---------------- helpers ----------------
__device__ __forceinline__ float cvt_tf32(float x) {
    unsigned u; asm("cvt.rna.tf32.f32 %0, %1;" : "=r"(u) : "f"(x));
    return __uint_as_float(u);
}

__device__ __forceinline__ void mma_tf32(float& c0, float& c1, float& c2, float& c3,
                                         unsigned a0, unsigned a1, unsigned a2, unsigned a3,
                                         unsigned b0, unsigned b1) {
    asm volatile("mma.sync.aligned.m16n8k8.row.col.f32.tf32.tf32.f32 "
                 "{%0,%1,%2,%3}, {%4,%5,%6,%7}, {%8,%9}, {%0,%1,%2,%3};"
                 : "+f"(c0), "+f"(c1), "+f"(c2), "+f"(c3)
                 : "r"(a0), "r"(a1), "r"(a2), "r"(a3), "r"(b0), "r"(b1));
}

__device__ __forceinline__ void ldsm4(unsigned& r0, unsigned& r1, unsigned& r2, unsigned& r3,
                                      unsigned addr) {
    asm volatile("ldmatrix.sync.aligned.m8n8.x4.shared.b16 {%0,%1,%2,%3}, [%4];"
                 : "=r"(r0), "=r"(r1), "=r"(r2), "=r"(r3) : "r"(addr));
}

__device__ __forceinline__ unsigned smem_u32(const void* p) {
    return (unsigned)__cvta_generic_to_shared(p);
}

__device__ __forceinline__ void cp16(float* smem_dst, const float* g_src) {
    unsigned s = (unsigned)__cvta_generic_to_shared(smem_dst);
    asm volatile("cp.async.cg.shared.global [%0], [%1], 16;" :: "r"(s), "l"(g_src));
}
__device__ __forceinline__ void cp_commit() {
    asm volatile("cp.async.commit_group;" ::: "memory");
}
__device__ __forceinline__ void cp_wait0() {
    asm volatile("cp.async.wait_group 0;" ::: "memory");
}

// sigmoid via MUFU
__device__ __forceinline__ float sigmoid_mufu(float x) {
    float e;
    asm("ex2.approx.f32 %0, %1;" : "=f"(e) : "f"(x * -1.4426950408889634f));
    float r;
    asm("rcp.approx.f32 %0, %1;" : "=f"(r) : "f"(1.0f + e));
    return r;
}

// ---------------- fused weight pre-round ----------------
__global__ __launch_bounds__(256) void cvt_all(
    const float4* __restrict__ w0, float4* __restrict__ o0,
    const float4* __restrict__ w1, float4* __restrict__ o1,
    const float4* __restrict__ w2, float4* __restrict__ o2,
    const float4* __restrict__ w3, float4* __restrict__ o3,
    const float4* __restrict__ w4, float4* __restrict__ o4)
{
    int i = blockIdx.x * 256 + threadIdx.x;
    const float4* src; float4* dst; int j;
    if      (i < 196608) { src = w0; dst = o0; j = i; }
    else if (i < 262144) { src = w1; dst = o1; j = i - 196608; }
    else if (i < 327680) { src = w2; dst = o2; j = i - 262144; }
    else if (i < 589824) { src = w3; dst = o3; j = i - 327680; }
    else                 { src = w4; dst = o4; j = i - 589824; }
    float4 v = src[j];
    v.x = cvt_tf32(v.x); v.y = cvt_tf32(v.y);
    v.z = cvt_tf32(v.z); v.w = cvt_tf32(v.w);
    dst[j] = v;
}

// ---------------- LayerNorm ----------------
__global__ __launch_bounds__(128) void ln_kernel(const float* __restrict__ x,
                                                 const float* __restrict__ g,
                                                 const float* __restrict__ bta,
                                                 float* __restrict__ out)
{
    int row = blockIdx.x;
    int t = threadIdx.x;
    const float4* xr = (const float4*)(x + (size_t)row * CCH);
    float4 v = xr[t];
    float s  = v.x + v.y + v.z + v.w;
    float s2 = v.x*v.x + v.y*v.y + v.z*v.z + v.w*v.w;
    #pragma unroll
    for (int o = 16; o; o >>= 1) {
        s  += __shfl_xor_sync(0xffffffffu, s,  o);
        s2 += __shfl_xor_sync(0xffffffffu, s2, o);
    }
    __shared__ float ss[4], ss2[4];
    int w = t >> 5, l = t & 31;
    if (l == 0) { ss[w] = s; ss2[w] = s2; }
    __syncthreads();
    s  = ss[0]  + ss[1]  + ss[2]  + ss[3];
    s2 = ss2[0] + ss2[1] + ss2[2] + ss2[3];
    float m   = s  * (1.0f/512.0f);
    float var = s2 * (1.0f/512.0f) - m*m;
    float r   = rsqrtf(var + 1e-5f);
    float4 gv = ((const float4*)g)[t];
    float4 bv = ((const float4*)bta)[t];
    float4 o4;
    o4.x = cvt_tf32((v.x - m) * r * gv.x + bv.x);
    o4.y = cvt_tf32((v.y - m) * r * gv.y + bv.y);
    o4.z = cvt_tf32((v.z - m) * r * gv.z + bv.z);
    o4.w = cvt_tf32((v.w - m) * r * gv.w + bv.w);
    ((float4*)(out + (size_t)row * CCH))[t] = o4;
}

// ---------------- TF32 GEMM: BM=128 BN=64 BK=32, 128 thr, 4 CTAs/SM (R10) ----------------
#define G_AS_STRIDE 36
#define G_BS_STRIDE 72
#define G_AS_SZ (128*G_AS_STRIDE)
#define G_BS_SZ (32*G_BS_STRIDE)
#define G_SMEM ((2*G_AS_SZ + 2*G_BS_SZ)*4)   // 55296 B

template<bool HAS_ADD, bool HAS_ADD2, bool GELU_EPI, bool ROUND_OUT>
__global__ __launch_bounds__(128, 4) void gemm_tf32(
    const float* __restrict__ A, const float* __restrict__ W,
    const float* __restrict__ bias,
    const float* __restrict__ addm, const float* __restrict__ addm2,
    float* __restrict__ Cmat, int M, int N, int K)
{
    extern __shared__ float sh[];
    float* As = sh;
    float* Bs = sh + 2*G_AS_SZ;

    const int tid  = threadIdx.x;
    const int warp = tid >> 5, lane = tid & 31;
    const int gid  = lane >> 2, tig = lane & 3;
    const int lg   = lane >> 3, lw = lane & 7;
    const int wm   = (warp >> 1) * 64;
    const int wn   = (warp & 1) * 32;
    const int bm   = blockIdx.y * 128, bn = blockIdx.x * 64;

    const int ar = tid >> 3, ac = (tid & 7) * 4;
    const int br = tid >> 4, bc = (tid & 15) * 4;

    const float* Ag = A + (size_t)bm * K;
    const float* Wg = W + bn;

    const unsigned as_u = smem_u32(As);
    const unsigned gA_off = ((wm + (lg & 1)*8 + lw) * G_AS_STRIDE + (lg >> 1)*4) * 4u;

    float acc[4][4][4] = {};
    const int nk = K >> 5;

    #pragma unroll
    for (int i = 0; i < 8; i++)
        cp16(As + (ar + i*16)*G_AS_STRIDE + ac, Ag + (size_t)(ar + i*16) * K + ac);
    #pragma unroll
    for (int i = 0; i < 4; i++)
        cp16(Bs + (br + i*8)*G_BS_STRIDE + bc, Wg + (size_t)(br + i*8) * N + bc);
    cp_commit();

    for (int kt = 0; kt < nk; kt++) {
        cp_wait0();
        __syncthreads();
        if (kt + 1 < nk) {
            int k0 = (kt + 1) << 5;
            float* asn = As + ((kt + 1) & 1) * G_AS_SZ;
            float* bsn = Bs + ((kt + 1) & 1) * G_BS_SZ;
            #pragma unroll
            for (int i = 0; i < 8; i++)
                cp16(asn + (ar + i*16)*G_AS_STRIDE + ac, Ag + (size_t)(ar + i*16) * K + k0 + ac);
            #pragma unroll
            for (int i = 0; i < 4; i++)
                cp16(bsn + (br + i*8)*G_BS_STRIDE + bc, Wg + (size_t)(k0 + br + i*8) * N + bc);
            cp_commit();
        }
        const unsigned as_b = as_u + (unsigned)((kt & 1) * G_AS_SZ * 4) + gA_off;
        const float* bs = Bs + (kt & 1) * G_BS_SZ;

        #pragma unroll
        for (int ks = 0; ks < 4; ks++) {
            unsigned af[4][4], bf[4][2];
            #pragma unroll
            for (int mt = 0; mt < 4; mt++)
                ldsm4(af[mt][0], af[mt][1], af[mt][2], af[mt][3],
                      as_b + (unsigned)((mt*16*G_AS_STRIDE + ks*8) * 4));
            #pragma unroll
            for (int nt = 0; nt < 4; nt++) {
                const float* bp = bs + (ks*8 + tig)*G_BS_STRIDE + wn + nt*8 + gid;
                bf[nt][0] = __float_as_uint(bp[0]);
                bf[nt][1] = __float_as_uint(bp[4*G_BS_STRIDE]);
            }
            #pragma unroll
            for (int mt = 0; mt < 4; mt++)
                #pragma unroll
                for (int nt = 0; nt < 4; nt++)
                    mma_tf32(acc[mt][nt][0], acc[mt][nt][1], acc[mt][nt][2], acc[mt][nt][3],
                             af[mt][0], af[mt][1], af[mt][2], af[mt][3],
                             bf[nt][0], bf[nt][1]);
        }
    }

    #pragma unroll
    for (int mt = 0; mt < 4; mt++) {
        int r0 = bm + wm + mt*16 + gid;
        #pragma unroll
        for (int nt = 0; nt < 4; nt++) {
            int c0 = bn + wn + nt*8 + 2*tig;
            float2 bv = *(const float2*)(bias + c0);
            float v0 = acc[mt][nt][0] + bv.x;
            float v1 = acc[mt][nt][1] + bv.y;
            float v2 = acc[mt][nt][2] + bv.x;
            float v3 = acc[mt][nt][3] + bv.y;
            size_t o0 = (size_t)r0 * N + c0;
            size_t o1 = (size_t)(r0 + 8) * N + c0;
            if (HAS_ADD) {
                float2 d0 = *(const float2*)(addm + o0);
                float2 d1 = *(const float2*)(addm + o1);
                v0 += d0.x; v1 += d0.y; v2 += d1.x; v3 += d1.y;
            }
            if (HAS_ADD2) {
                float2 d0 = *(const float2*)(addm2 + o0);
                float2 d1 = *(const float2*)(addm2 + o1);
                v0 += d0.x; v1 += d0.y; v2 += d1.x; v3 += d1.y;
            }
            if (GELU_EPI) {
                v0 = 0.5f * v0 * (1.0f + erff(v0 * 0.70710678118654752f));
                v1 = 0.5f * v1 * (1.0f + erff(v1 * 0.70710678118654752f));
                v2 = 0.5f * v2 * (1.0f + erff(v2 * 0.70710678118654752f));
                v3 = 0.5f * v3 * (1.0f + erff(v3 * 0.70710678118654752f));
            }
            if (ROUND_OUT) {
                v0 = cvt_tf32(v0); v1 = cvt_tf32(v1);
                v2 = cvt_tf32(v2); v3 = cvt_tf32(v3);
            }
            *(float2*)(Cmat + o0) = make_float2(v0, v1);
            *(float2*)(Cmat + o1) = make_float2(v2, v3);
        }
    }
}

// ---------------- attention: mt=2 (32 t-rows/warp), 128 thr, s-split x2 ----------------
#define A_KS_STRIDE 68
#define A_VS_STRIDE 72
#define A_SS_STRIDE 36
#define A_KS_SZ (64*A_KS_STRIDE)
#define A_VS_SZ (64*A_VS_STRIDE)
#define A_SMEM ((2*A_KS_SZ + 2*A_VS_SZ + 128*A_SS_STRIDE)*4)   // 90112 B
#define NKT (TT/64)

__global__ __launch_bounds__(128, 2) void attn_tf32(const float* __restrict__ qkv,
                                                    const float* __restrict__ coul,
                                                    float* __restrict__ yatt0,
                                                    float* __restrict__ yatt1)
{
    extern __shared__ float sh[];
    float* Ks = sh;
    float* Vs = sh + 2*A_KS_SZ;
    float* Ss = Vs + 2*A_VS_SZ;

    const int bh = blockIdx.x;                 // heads fastest -> coulomb L2 sharing
    const int b = bh >> 3, h = bh & 7;
    const int ttile = blockIdx.y >> 1;
    const int shalf = blockIdx.y & 1;
    const int t0 = ttile * 128;
    const int kt0 = shalf * (NKT/2), kt1 = kt0 + (NKT/2);
    const int tid = threadIdx.x, warp = tid >> 5, lane = tid & 31;
    const int gid = lane >> 2, tig = lane & 3;
    const int lg = lane >> 3, lw = lane & 7;
    const int lr = tid >> 4, lc = (tid & 15) * 4;   // K/V loader: 8 rows/pass
    const int rw = warp * 32;                       // warp row base (4 warps x 32)

    const unsigned ks_u = smem_u32(Ks);
    const unsigned ss_u = smem_u32(Ss);
    const unsigned qkB_off = (((lg >> 1)*8 + lw) * A_KS_STRIDE + (lg & 1)*4) * 4u;
    // PV A-frag ldmatrix offsets per mt
    const unsigned pvA0 = ((rw + (lg & 1)*8 + lw) * A_SS_STRIDE + (lg >> 1)*4) * 4u;
    const unsigned pvA1 = pvA0 + (unsigned)(16 * A_SS_STRIDE * 4);

    // Q fragments in registers for both m16 tiles (rows rw+mt*16+{gid,gid+8})
    float qf[2][8][4];
    #pragma unroll
    for (int mt = 0; mt < 2; mt++) {
        const float* q0 = qkv + (size_t)(b*TT + t0 + rw + mt*16 + gid) * C3 + h*DD;
        #pragma unroll
        for (int kd = 0; kd < 8; kd++) {
            qf[mt][kd][0] = q0[kd*8 + tig]            * 0.125f;
            qf[mt][kd][1] = q0[8*C3 + kd*8 + tig]     * 0.125f;
            qf[mt][kd][2] = q0[kd*8 + tig + 4]        * 0.125f;
            qf[mt][kd][3] = q0[8*C3 + kd*8 + tig + 4] * 0.125f;
        }
    }

    float yacc[2][8][4];
    #pragma unroll
    for (int mt = 0; mt < 2; mt++)
        #pragma unroll
        for (int i = 0; i < 8; i++)
            { yacc[mt][i][0]=0.f; yacc[mt][i][1]=0.f; yacc[mt][i][2]=0.f; yacc[mt][i][3]=0.f; }

    const float* cb[2];
    cb[0] = coul + (size_t)b * TT * TT + (size_t)(t0 + rw + gid) * TT;
    cb[1] = cb[0] + (size_t)16 * TT;
    const float* kbase = qkv + (size_t)(b*TT) * C3 + CCH + h*DD;

    // prologue: cp.async first s-tile of this half (64 rows, 8 per pass)
    {
        const float* k0p = kbase + (size_t)(kt0 * 64) * C3;
        float* kd_ = Ks + (kt0 & 1) * A_KS_SZ;
        float* vd_ = Vs + (kt0 & 1) * A_VS_SZ;
        #pragma unroll
        for (int i = 0; i < 8; i++) {
            int r = lr + i*8;
            cp16(kd_ + r*A_KS_STRIDE + lc, k0p + (size_t)r * C3 + lc);
            cp16(vd_ + r*A_VS_STRIDE + lc, k0p + CCH + (size_t)r * C3 + lc);
        }
        cp_commit();
    }

    for (int kt = kt0; kt < kt1; kt++) {
        cp_wait0();
        __syncthreads();
        if (kt + 1 < kt1) {
            const float* kn = kbase + (size_t)((kt + 1) * 64) * C3;
            float* kd_ = Ks + ((kt + 1) & 1) * A_KS_SZ;
            float* vd_ = Vs + ((kt + 1) & 1) * A_VS_SZ;
            #pragma unroll
            for (int i = 0; i < 8; i++) {
                int r = lr + i*8;
                cp16(kd_ + r*A_KS_STRIDE + lc, kn + (size_t)r * C3 + lc);
                cp16(vd_ + r*A_VS_STRIDE + lc, kn + CCH + (size_t)r * C3 + lc);
            }
            cp_commit();
        }
        const unsigned ksb_u = ks_u + (unsigned)((kt & 1) * A_KS_SZ * 4) + qkB_off;
        const float* vsb = Vs + (kt & 1) * A_VS_SZ;
        const int s0 = kt * 64;

        #pragma unroll
        for (int hf = 0; hf < 2; hf++) {
            // coulomb prefetch (rows gid/gid+8 per mt)
            float2 c0[2][4], c1[2][4];
            #pragma unroll
            for (int mt = 0; mt < 2; mt++)
                #pragma unroll
                for (int nt = 0; nt < 4; nt++) {
                    int sc = s0 + hf*32 + nt*8 + 2*tig;
                    c0[mt][nt] = *(const float2*)(cb[mt] + sc);
                    c1[mt][nt] = *(const float2*)(cb[mt] + 8*TT + sc);
                }

            // S = Q @ K^T : each K ldmatrix feeds BOTH mt tiles
            float sacc[2][4][4];
            #pragma unroll
            for (int mt = 0; mt < 2; mt++)
                #pragma unroll
                for (int i = 0; i < 4; i++)
                    { sacc[mt][i][0]=0.f; sacc[mt][i][1]=0.f; sacc[mt][i][2]=0.f; sacc[mt][i][3]=0.f; }
            #pragma unroll
            for (int kd = 0; kd < 8; kd++) {
                #pragma unroll
                for (int p = 0; p < 2; p++) {
                    unsigned b0e, b1e, b0o, b1o;
                    ldsm4(b0e, b1e, b0o, b1o,
                          ksb_u + (unsigned)(((hf*32 + p*16)*A_KS_STRIDE + kd*8) * 4));
                    #pragma unroll
                    for (int mt = 0; mt < 2; mt++) {
                        mma_tf32(sacc[mt][2*p][0], sacc[mt][2*p][1], sacc[mt][2*p][2], sacc[mt][2*p][3],
                                 __float_as_uint(qf[mt][kd][0]), __float_as_uint(qf[mt][kd][1]),
                                 __float_as_uint(qf[mt][kd][2]), __float_as_uint(qf[mt][kd][3]),
                                 b0e, b1e);
                        mma_tf32(sacc[mt][2*p+1][0], sacc[mt][2*p+1][1], sacc[mt][2*p+1][2], sacc[mt][2*p+1][3],
                                 __float_as_uint(qf[mt][kd][0]), __float_as_uint(qf[mt][kd][1]),
                                 __float_as_uint(qf[mt][kd][2]), __float_as_uint(qf[mt][kd][3]),
                                 b0o, b1o);
                    }
                }
            }

            // sigmoid(MUFU) * coulomb -> Ss (warp-private rows)
            #pragma unroll
            for (int mt = 0; mt < 2; mt++)
                #pragma unroll
                for (int nt = 0; nt < 4; nt++) {
                    float* sp = Ss + (rw + mt*16 + gid)*A_SS_STRIDE + nt*8 + 2*tig;
                    *(float2*)(sp) = make_float2(
                        cvt_tf32(sigmoid_mufu(sacc[mt][nt][0]) * c0[mt][nt].x),
                        cvt_tf32(sigmoid_mufu(sacc[mt][nt][1]) * c0[mt][nt].y));
                    *(float2*)(sp + 8*A_SS_STRIDE) = make_float2(
                        cvt_tf32(sigmoid_mufu(sacc[mt][nt][2]) * c1[mt][nt].x),
                        cvt_tf32(sigmoid_mufu(sacc[mt][nt][3]) * c1[mt][nt].y));
                }
            __syncwarp();

            // Y += S_half @ V_half : each V load feeds BOTH mt tiles
            #pragma unroll
            for (int ks = 0; ks < 4; ks++) {
                unsigned a0[2], a1[2], a2[2], a3[2];
                ldsm4(a0[0], a1[0], a2[0], a3[0], ss_u + pvA0 + (unsigned)(ks*8*4));
                ldsm4(a0[1], a1[1], a2[1], a3[1], ss_u + pvA1 + (unsigned)(ks*8*4));
                #pragma unroll
                for (int nt = 0; nt < 8; nt++) {
                    const float* bp = vsb + (hf*32 + ks*8 + tig)*A_VS_STRIDE + nt*8 + gid;
                    unsigned bv0 = __float_as_uint(bp[0]);
                    unsigned bv1 = __float_as_uint(bp[4*A_VS_STRIDE]);
                    mma_tf32(yacc[0][nt][0], yacc[0][nt][1], yacc[0][nt][2], yacc[0][nt][3],
                             a0[0], a1[0], a2[0], a3[0], bv0, bv1);
                    mma_tf32(yacc[1][nt][0], yacc[1][nt][1], yacc[1][nt][2], yacc[1][nt][3],
                             a0[1], a1[1], a2[1], a3[1], bv0, bv1);
                }
            }
            __syncwarp();
        }
    }

    // store partial Y
    float* ybuf = shalf ? yatt1 : yatt0;
    #pragma unroll
    for (int mt = 0; mt < 2; mt++) {
        float* ob = ybuf + (size_t)(b*TT + t0 + rw + mt*16 + gid) * CCH + h*DD;
        #pragma unroll
        for (int nt = 0; nt < 8; nt++) {
            int c = nt*8 + 2*tig;
            *(float2*)(ob + c)         = make_float2(yacc[mt][nt][0], yacc[mt][nt][1]);
            *(float2*)(ob + 8*CCH + c) = make_float2(yacc[mt][nt][2], yacc[mt][nt][3]);
        }
    }
}

// ---------------- launch ----------------
extern "C" void kernel_launch(void* const* d_in, const int* in_sizes, int n_in,
                              void* d_out, int out_size)
{
    const float* x      = (const float*)d_in[0];
    const float* coul   = (const float*)d_in[2];
    const float* ln1g   = (const float*)d_in[3];
    const float* ln1b   = (const float*)d_in[4];
    const float* w_attn = (const float*)d_in[5];
    const float* b_attn = (const float*)d_in[6];
    const float* w_self = (const float*)d_in[7];
    const float* b_self = (const float*)d_in[8];
    const float* w_proj = (const float*)d_in[9];
    const float* b_proj = (const float*)d_in[10];
    const float* ln2g   = (const float*)d_in[11];
    const float* ln2b   = (const float*)d_in[12];
    const float* w_fc   = (const float*)d_in[13];
    const float* b_fc   = (const float*)d_in[14];
    const float* w_fcp  = (const float*)d_in[15];
    const float* b_fcp  = (const float*)d_in[16];
    float* out = (float*)d_out;

    float *h, *qkvp, *att0, *att1, *yp, *y2p, *h2p, *fcp;
    float *wattn, *wself, *wproj, *wfc, *wfcp;
    cudaGetSymbolAddress((void**)&h,    g_h);
    cudaGetSymbolAddress((void**)&qkvp, g_qkv);
    cudaGetSymbolAddress((void**)&att0, g_att0);
    cudaGetSymbolAddress((void**)&att1, g_att1);
    cudaGetSymbolAddress((void**)&yp,   g_y);
    cudaGetSymbolAddress((void**)&y2p,  g_y2);
    cudaGetSymbolAddress((void**)&h2p,  g_h2);
    cudaGetSymbolAddress((void**)&fcp,  g_fc);
    cudaGetSymbolAddress((void**)&wattn, g_wattn);
    cudaGetSymbolAddress((void**)&wself, g_wself);
    cudaGetSymbolAddress((void**)&wproj, g_wproj);
    cudaGetSymbolAddress((void**)&wfc,   g_wfc);
    cudaGetSymbolAddress((void**)&wfcp,  g_wfcp);

    cudaFuncSetAttribute((const void*)gemm_tf32<false,false,false,true>,  cudaFuncAttributeMaxDynamicSharedMemorySize, G_SMEM);
    cudaFuncSetAttribute((const void*)gemm_tf32<false,false,true,true>,   cudaFuncAttributeMaxDynamicSharedMemorySize, G_SMEM);
    cudaFuncSetAttribute((const void*)gemm_tf32<true,true,false,true>,    cudaFuncAttributeMaxDynamicSharedMemorySize, G_SMEM);
    cudaFuncSetAttribute((const void*)gemm_tf32<false,false,false,false>, cudaFuncAttributeMaxDynamicSharedMemorySize, G_SMEM);
    cudaFuncSetAttribute(attn_tf32, cudaFuncAttributeMaxDynamicSharedMemorySize, A_SMEM);

    // 0) pre-round weights to tf32
    cvt_all<<<3328, 256>>>((const float4*)w_attn, (float4*)wattn,
                           (const float4*)w_self, (float4*)wself,
                           (const float4*)w_proj, (float4*)wproj,
                           (const float4*)w_fc,   (float4*)wfc,
                           (const float4*)w_fcp,  (float4*)wfcp);

    // 1) h = LN1(x)
    ln_kernel<<<NROWS, 128>>>(x, ln1g, ln1b, h);
    // 2) qkv = h @ w_attn + b_attn
    gemm_tf32<false,false,false,true><<<dim3(24,32), 128, G_SMEM>>>(h, wattn, b_attn, nullptr, nullptr, qkvp, NROWS, C3, CCH);
    // 3) attention, s-split x2, mt=2 warps
    attn_tf32<<<dim3(BB*HH, (TT/128)*2), 128, A_SMEM>>>(qkvp, coul, att0, att1);
    // 4) y = att0 + att1 + h @ w_self + b_self
    gemm_tf32<true,true,false,true><<<dim3(8,32), 128, G_SMEM>>>(h, wself, b_self, att0, att1, yp, NROWS, CCH, CCH);
    // 5) y2 = y @ w_proj + b_proj
    gemm_tf32<false,false,false,false><<<dim3(8,32), 128, G_SMEM>>>(yp, wproj, b_proj, nullptr, nullptr, y2p, NROWS, CCH, CCH);
    // 6) h2 = LN2(y2)
    ln_kernel<<<NROWS, 128>>>(y2p, ln2g, ln2b, h2p);
    // 7) fc = gelu(h2 @ w_fc + b_fc)
    gemm_tf32<false,false,true,true><<<dim3(32,32), 128, G_SMEM>>>(h2p, wfc, b_fc, nullptr, nullptr, fcp, NROWS, 4*CCH, CCH);
    // 8) out = fc @ w_fc_proj + b_fc_proj
    gemm_tf32<false,false,false,false><<<dim3(8,32), 128, G_SMEM>>>(fcp, wfcp, b_fcp, nullptr, nullptr, out, NROWS, CCH, 4*CCH);
}